// round 12
// baseline (speedup 1.0000x reference)
#include <cuda_runtime.h>
#include <cuda_fp16.h>
#include <math.h>
#include <stdint.h>

#define PP 8192
#define DDIM 512

// ---- scratch (device globals) ----
__device__ __half g_Qh[PP * DDIM];
__device__ __half g_Kh[PP * DDIM];
__device__ __half g_Fh[PP * DDIM];
__device__ __half g_Vth[DDIM * PP];          // V transposed: [feature][position]
__device__ __half g_Th[(size_t)PP * PP];     // unnormalized exp probs (fp16), 128 MB
__device__ float  g_psum[(size_t)PP * 64];   // per (row, colTile) partial sums
__device__ float  g_norm[PP];
__device__ float  g_tdiag[PP];
__device__ float  g_inv[PP];

// ---------------- helpers ----------------
__device__ __forceinline__ uint32_t s2u(const void* p) {
    return (uint32_t)__cvta_generic_to_shared(p);
}
__device__ __forceinline__ uint32_t f2h2(float a, float b) {
    __half2 h = __floats2half2_rn(a, b);
    return *reinterpret_cast<uint32_t*>(&h);
}
// tile rows of 32 halves (64B), 16B chunks XOR-swizzled
__device__ __forceinline__ int swz64(int r, int c) {
    return r * 64 + ((c ^ ((r >> 1) & 3)) << 4);
}
__device__ __forceinline__ void mma16(float* d, const uint32_t* a, const uint32_t* b) {
    asm volatile(
        "mma.sync.aligned.m16n8k16.row.col.f32.f16.f16.f32 "
        "{%0,%1,%2,%3},{%4,%5,%6,%7},{%8,%9},{%0,%1,%2,%3};"
        : "+f"(d[0]), "+f"(d[1]), "+f"(d[2]), "+f"(d[3])
        : "r"(a[0]), "r"(a[1]), "r"(a[2]), "r"(a[3]), "r"(b[0]), "r"(b[1]));
}
__device__ __forceinline__ void ldsm4(uint32_t addr, uint32_t* r) {
    asm volatile("ldmatrix.sync.aligned.m8n8.x4.shared.b16 {%0,%1,%2,%3}, [%4];"
        : "=r"(r[0]), "=r"(r[1]), "=r"(r[2]), "=r"(r[3]) : "r"(addr));
}
__device__ __forceinline__ void fragA(uint32_t tbase, int R, int ks, int lane, uint32_t* a) {
    int mi = lane >> 3, ri = lane & 7;
    int r = R + ri + (mi & 1) * 8;
    int c = ks * 2 + (mi >> 1);
    ldsm4(tbase + swz64(r, c), a);
}
__device__ __forceinline__ void fragB(uint32_t tbase, int N0, int ks, int lane, uint32_t* b) {
    int mi = lane >> 3, ri = lane & 7;
    int r = N0 + ri + (mi >> 1) * 8;
    int c = ks * 2 + (mi & 1);
    ldsm4(tbase + swz64(r, c), b);
}
// ---- cp.async ----
__device__ __forceinline__ void cpa16(uint32_t dst, const void* src) {
    asm volatile("cp.async.cg.shared.global [%0], [%1], 16;" :: "r"(dst), "l"(src));
}
__device__ __forceinline__ void cp_commit() {
    asm volatile("cp.async.commit_group;" ::: "memory");
}
template<int N>
__device__ __forceinline__ void cp_wait() {
    asm volatile("cp.async.wait_group %0;" :: "n"(N) : "memory");
}

// ------- reg-staged tiles for qkv -------
struct U8 { uint4 a, b; };
__device__ __forceinline__ U8 ldgH(const __half* g, size_t ld, int kb, int tid) {
    int row = tid >> 1, c0 = (tid & 1) * 16;
    const __half* p = g + (size_t)row * ld + kb + c0;
    U8 r; r.a = *(const uint4*)p; r.b = *(const uint4*)(p + 8);
    return r;
}
__device__ __forceinline__ void stsH(char* tile, U8 s, int tid) {
    int row = tid >> 1, c0 = (tid & 1) * 2;
    *(uint4*)(tile + swz64(row, c0))     = s.a;
    *(uint4*)(tile + swz64(row, c0 + 1)) = s.b;
}
struct W8 { float4 a, b; };
__device__ __forceinline__ W8 ldgW(const float* g, int ld, int kb, int tid) {
    int row = tid >> 2, c = tid & 3;
    const float* p = g + (size_t)row * ld + kb + c * 8;
    W8 r; r.a = *(const float4*)p; r.b = *(const float4*)(p + 4);
    return r;
}
__device__ __forceinline__ void stsW(char* tile, W8 s, int tid) {
    int row = tid >> 2, c = tid & 3;
    uint4 h;
    h.x = f2h2(s.a.x, s.a.y); h.y = f2h2(s.a.z, s.a.w);
    h.z = f2h2(s.b.x, s.b.y); h.w = f2h2(s.b.z, s.b.w);
    *(uint4*)(tile + swz64(row, c)) = h;
}

// ============================================================
// Kernel 1: row norms of F + convert F -> g_Fh
// ============================================================
__global__ void norm_cvt_kernel(const float* __restrict__ F)
{
    int row = blockIdx.x, tid = threadIdx.x;   // 128 threads
    const float4* fr = (const float4*)(F + (size_t)row * DDIM);
    float4 v = fr[tid];
    float s = v.x*v.x + v.y*v.y + v.z*v.z + v.w*v.w;
    uint2 h; h.x = f2h2(v.x, v.y); h.y = f2h2(v.z, v.w);
    *(uint2*)(g_Fh + (size_t)row * DDIM + tid * 4) = h;
    #pragma unroll
    for (int o = 16; o > 0; o >>= 1) s += __shfl_xor_sync(0xffffffffu, s, o);
    __shared__ float red[4];
    if ((tid & 31) == 0) red[tid >> 5] = s;
    __syncthreads();
    if (tid == 0) g_norm[row] = red[0] + red[1] + red[2] + red[3];
}

// ============================================================
// Kernel 2: Q/K/V = F @ W^T + b (fp16 mma). Outputs Qh,Kh,Vth.
// ============================================================
__global__ __launch_bounds__(256) void qkv_h(
    const float* __restrict__ Wq, const float* __restrict__ bq,
    const float* __restrict__ Wk, const float* __restrict__ bk,
    const float* __restrict__ Wv, const float* __restrict__ bv)
{
    __shared__ char smem[2 * 20 * 1024];
    const int tid = threadIdx.x, lane = tid & 31, wid = tid >> 5;
    const int wm = wid & 3, wn = wid >> 2;
    const int rowBase = blockIdx.y * 128, colBase = blockIdx.x * 64;

    float aq[2][4][4] = {}, ak[2][4][4] = {}, avv[2][4][4] = {};

    const __half* Fb = g_Fh + (size_t)rowBase * DDIM;
    const float* Qb = Wq + (size_t)colBase * DDIM;
    const float* Kb = Wk + (size_t)colBase * DDIM;
    const float* Vb = Wv + (size_t)colBase * DDIM;

    U8 pf = ldgH(Fb, DDIM, 0, tid);
    W8 pq = ldgW(Qb, DDIM, 0, tid);
    W8 pk = ldgW(Kb, DDIM, 0, tid);
    W8 pv = ldgW(Vb, DDIM, 0, tid);
    char* buf0 = smem; char* buf1 = smem + 20 * 1024;
    stsH(buf0, pf, tid);
    stsW(buf0 +  8192, pq, tid);
    stsW(buf0 + 12288, pk, tid);
    stsW(buf0 + 16384, pv, tid);
    __syncthreads();

    const int NKB = DDIM / 32;   // 16
    for (int kb = 0; kb < NKB; kb++) {
        if (kb + 1 < NKB) {
            int k = (kb + 1) * 32;
            pf = ldgH(Fb, DDIM, k, tid);
            pq = ldgW(Qb, DDIM, k, tid);
            pk = ldgW(Kb, DDIM, k, tid);
            pv = ldgW(Vb, DDIM, k, tid);
        }
        uint32_t su = s2u((kb & 1) ? buf1 : buf0);
        #pragma unroll
        for (int ks = 0; ks < 2; ks++) {
            uint32_t a[2][4];
            fragA(su, wm * 32,      ks, lane, a[0]);
            fragA(su, wm * 32 + 16, ks, lane, a[1]);
            #pragma unroll
            for (int p = 0; p < 2; p++) {
                uint32_t b[4];
                fragB(su + 8192, wn * 32 + p * 16, ks, lane, b);
                #pragma unroll
                for (int tm = 0; tm < 2; tm++) {
                    mma16(aq[tm][2*p],   a[tm], b);
                    mma16(aq[tm][2*p+1], a[tm], b + 2);
                }
                fragB(su + 12288, wn * 32 + p * 16, ks, lane, b);
                #pragma unroll
                for (int tm = 0; tm < 2; tm++) {
                    mma16(ak[tm][2*p],   a[tm], b);
                    mma16(ak[tm][2*p+1], a[tm], b + 2);
                }
                fragB(su + 16384, wn * 32 + p * 16, ks, lane, b);
                #pragma unroll
                for (int tm = 0; tm < 2; tm++) {
                    mma16(avv[tm][2*p],   a[tm], b);
                    mma16(avv[tm][2*p+1], a[tm], b + 2);
                }
            }
        }
        char* nxt = (kb & 1) ? buf0 : buf1;
        if (kb + 1 < NKB) {
            stsH(nxt, pf, tid);
            stsW(nxt +  8192, pq, tid);
            stsW(nxt + 12288, pk, tid);
            stsW(nxt + 16384, pv, tid);
        }
        __syncthreads();
    }

    const int gr = lane >> 2, tg = lane & 3;
    #pragma unroll
    for (int tm = 0; tm < 2; tm++) {
        int r0 = rowBase + wm * 32 + tm * 16 + gr, r1 = r0 + 8;
        #pragma unroll
        for (int tn = 0; tn < 4; tn++) {
            int c = colBase + wn * 32 + tn * 8 + 2 * tg;
            float bq0 = bq[c], bq1 = bq[c+1];
            float bk0 = bk[c], bk1 = bk[c+1];
            float bv0 = bv[c], bv1 = bv[c+1];
            float* A = aq[tm][tn];
            *(uint32_t*)(g_Qh + (size_t)r0 * DDIM + c) = f2h2(A[0] + bq0, A[1] + bq1);
            *(uint32_t*)(g_Qh + (size_t)r1 * DDIM + c) = f2h2(A[2] + bq0, A[3] + bq1);
            A = ak[tm][tn];
            *(uint32_t*)(g_Kh + (size_t)r0 * DDIM + c) = f2h2(A[0] + bk0, A[1] + bk1);
            *(uint32_t*)(g_Kh + (size_t)r1 * DDIM + c) = f2h2(A[2] + bk0, A[3] + bk1);
            A = avv[tm][tn];
            g_Vth[(size_t)c     * PP + r0] = __float2half(A[0] + bv0);
            g_Vth[(size_t)(c+1) * PP + r0] = __float2half(A[1] + bv1);
            g_Vth[(size_t)c     * PP + r1] = __float2half(A[2] + bv0);
            g_Vth[(size_t)(c+1) * PP + r1] = __float2half(A[3] + bv1);
        }
    }
}

// ============================================================
// Kernel 3: tdiag[i] = (Q_i . K_i) / sqrt(d)
// ============================================================
__global__ void diag_kernel()
{
    int row = blockIdx.x, tid = threadIdx.x;   // 128 threads
    const __half* Q = g_Qh + (size_t)row * DDIM + tid * 4;
    const __half* K = g_Kh + (size_t)row * DDIM + tid * 4;
    uint2 qa = *(const uint2*)Q;
    uint2 ka = *(const uint2*)K;
    __half2 q0 = *(__half2*)&qa.x, q1 = *(__half2*)&qa.y;
    __half2 k0 = *(__half2*)&ka.x, k1 = *(__half2*)&ka.y;
    float2 qf0 = __half22float2(q0), qf1 = __half22float2(q1);
    float2 kf0 = __half22float2(k0), kf1 = __half22float2(k1);
    float s = qf0.x*kf0.x + qf0.y*kf0.y + qf1.x*kf1.x + qf1.y*kf1.y;
    #pragma unroll
    for (int o = 16; o > 0; o >>= 1) s += __shfl_xor_sync(0xffffffffu, s, o);
    __shared__ float red[4];
    if ((tid & 31) == 0) red[tid >> 5] = s;
    __syncthreads();
    if (tid == 0)
        g_tdiag[row] = (red[0] + red[1] + red[2] + red[3]) * 0.044194173824159216f;
}

// ============================================================
// Kernel 4: dist via G=FF^T, lower-triangle tiles only (bx<=by).
// 128x128 tile, warp 32x64, 4-stage cp.async (16KB/stage).
// Writes dist[r][c] direct + mirrored dist[c][r] via smem transpose.
// ============================================================
__device__ __forceinline__ void ds_issue(uint32_t sbase, int stg, int kb, int tid,
    const __half* Fr, const __half* Fc)
{
    int row = tid >> 1;
    int ch0 = (tid & 1) * 2;
    uint32_t so = sbase + stg * 16384;
    size_t off = (size_t)row * DDIM + kb + ch0 * 8;
    cpa16(so +        swz64(row, ch0),     Fr + off);
    cpa16(so +        swz64(row, ch0 + 1), Fr + off + 8);
    cpa16(so + 8192 + swz64(row, ch0),     Fc + off);
    cpa16(so + 8192 + swz64(row, ch0 + 1), Fc + off + 8);
}

__global__ __launch_bounds__(256, 2) void dist_sym(float* __restrict__ dist_out)
{
    if (blockIdx.x > blockIdx.y) return;
    extern __shared__ char dsm[];
    const uint32_t sbase = s2u(dsm);
    const int tid = threadIdx.x, lane = tid & 31, wid = tid >> 5;
    const int wm = wid & 3, wn = wid >> 2;
    const int rowBase = blockIdx.y * 128, colBase = blockIdx.x * 128;

    float acc[2][8][4] = {};

    const __half* Fr = g_Fh + (size_t)rowBase * DDIM;
    const __half* Fc = g_Fh + (size_t)colBase * DDIM;

    const int NKB = DDIM / 32;   // 16
    #pragma unroll
    for (int s = 0; s < 3; s++) {
        ds_issue(sbase, s, s * 32, tid, Fr, Fc);
        cp_commit();
    }

    for (int kb = 0; kb < NKB; kb++) {
        cp_wait<2>();
        __syncthreads();
        if (kb + 3 < NKB)
            ds_issue(sbase, (kb + 3) & 3, (kb + 3) * 32, tid, Fr, Fc);
        cp_commit();

        uint32_t su = sbase + (kb & 3) * 16384;
        #pragma unroll
        for (int ks = 0; ks < 2; ks++) {
            uint32_t a[2][4];
            fragA(su, wm * 32,      ks, lane, a[0]);
            fragA(su, wm * 32 + 16, ks, lane, a[1]);
            #pragma unroll
            for (int p = 0; p < 4; p++) {
                uint32_t b[4];
                fragB(su + 8192, wn * 64 + p * 16, ks, lane, b);
                #pragma unroll
                for (int tm = 0; tm < 2; tm++) {
                    mma16(acc[tm][2*p],   a[tm], b);
                    mma16(acc[tm][2*p+1], a[tm], b + 2);
                }
            }
        }
    }
    cp_wait<0>();
    __syncthreads();

    // epilogue: dist = sqrt(max(nr + nc - 2G, 0)); direct write + smem transpose
    float* st = (float*)dsm;   // [128][132] floats
    const int gr = lane >> 2, tg = lane & 3;
    #pragma unroll
    for (int tm = 0; tm < 2; tm++) {
        int rl0 = wm * 32 + tm * 16 + gr, rl1 = rl0 + 8;
        int r0 = rowBase + rl0, r1 = rowBase + rl1;
        float n0 = g_norm[r0], n1 = g_norm[r1];
        #pragma unroll
        for (int tn = 0; tn < 8; tn++) {
            int cl = wn * 64 + tn * 8 + 2 * tg;
            int c = colBase + cl;
            float nc0 = g_norm[c], nc1 = g_norm[c+1];
            float* A = acc[tm][tn];
            float d00 = sqrtf(fmaxf(n0 + nc0 - 2.f * A[0], 0.f));
            float d01 = sqrtf(fmaxf(n0 + nc1 - 2.f * A[1], 0.f));
            float d10 = sqrtf(fmaxf(n1 + nc0 - 2.f * A[2], 0.f));
            float d11 = sqrtf(fmaxf(n1 + nc1 - 2.f * A[3], 0.f));
            *(float2*)(dist_out + (size_t)r0 * PP + c) = make_float2(d00, d01);
            *(float2*)(dist_out + (size_t)r1 * PP + c) = make_float2(d10, d11);
            st[(cl    ) * 132 + rl0] = d00;
            st[(cl + 1) * 132 + rl0] = d01;
            st[(cl    ) * 132 + rl1] = d10;
            st[(cl + 1) * 132 + rl1] = d11;
        }
    }
    __syncthreads();
    if (blockIdx.x != blockIdx.y) {
        int i = tid >> 1;                 // 0..127: row of transposed tile
        int j0 = (tid & 1) * 64;
        const float* srow = st + i * 132 + j0;
        float* orow = dist_out + (size_t)(colBase + i) * PP + rowBase + j0;
        #pragma unroll
        for (int j = 0; j < 64; j += 4)
            *(float4*)(orow + j) = *(const float4*)(srow + j);
    }
}

// ============================================================
// Kernel 5: S=QK^T (128x128 tile, warp 32x64). Epilogue reads dist,
// computes E=exp(S*isd - lam*d - td) -> g_Th, psum -> g_psum.
// ============================================================
__device__ __forceinline__ void ls_issue(uint32_t sbase, int stg, int kb, int tid,
    const __half* Qb, const __half* Kb)
{
    int row = tid >> 1;
    int ch0 = (tid & 1) * 2;
    uint32_t so = sbase + stg * 16384;
    size_t off = (size_t)row * DDIM + kb + ch0 * 8;
    cpa16(so +        swz64(row, ch0),     Qb + off);
    cpa16(so +        swz64(row, ch0 + 1), Qb + off + 8);
    cpa16(so + 8192 + swz64(row, ch0),     Kb + off);
    cpa16(so + 8192 + swz64(row, ch0 + 1), Kb + off + 8);
}

__global__ __launch_bounds__(256, 2) void logits_s(
    const float* __restrict__ lamP, const float* __restrict__ dist_in)
{
    extern __shared__ char dsm[];
    __shared__ float ps[128][2];
    const uint32_t sbase = s2u(dsm);
    const int tid = threadIdx.x, lane = tid & 31, wid = tid >> 5;
    const int wm = wid & 3, wn = wid >> 2;
    const int rowBase = blockIdx.y * 128, colBase = blockIdx.x * 128;

    float acc[2][8][4] = {};

    const __half* Qb = g_Qh + (size_t)rowBase * DDIM;
    const __half* Kb = g_Kh + (size_t)colBase * DDIM;

    const int NKB = DDIM / 32;   // 16
    #pragma unroll
    for (int s = 0; s < 3; s++) {
        ls_issue(sbase, s, s * 32, tid, Qb, Kb);
        cp_commit();
    }

    for (int kb = 0; kb < NKB; kb++) {
        cp_wait<2>();
        __syncthreads();
        if (kb + 3 < NKB)
            ls_issue(sbase, (kb + 3) & 3, (kb + 3) * 32, tid, Qb, Kb);
        cp_commit();

        uint32_t su = sbase + (kb & 3) * 16384;
        #pragma unroll
        for (int ks = 0; ks < 2; ks++) {
            uint32_t a[2][4];
            fragA(su, wm * 32,      ks, lane, a[0]);
            fragA(su, wm * 32 + 16, ks, lane, a[1]);
            #pragma unroll
            for (int p = 0; p < 4; p++) {
                uint32_t b[4];
                fragB(su + 8192, wn * 64 + p * 16, ks, lane, b);
                #pragma unroll
                for (int tm = 0; tm < 2; tm++) {
                    mma16(acc[tm][2*p],   a[tm], b);
                    mma16(acc[tm][2*p+1], a[tm], b + 2);
                }
            }
        }
    }

    const int gr = lane >> 2, tg = lane & 3;
    const float lam = *lamP;
    const float isd = 0.044194173824159216f;  // 1/sqrt(512)
    float rs[2][2];
    #pragma unroll
    for (int tm = 0; tm < 2; tm++) {
        int r0 = rowBase + wm * 32 + tm * 16 + gr, r1 = r0 + 8;
        float td0 = g_tdiag[r0], td1 = g_tdiag[r1];
        float s0 = 0.f, s1 = 0.f;
        #pragma unroll
        for (int tn = 0; tn < 8; tn++) {
            int c = colBase + wn * 64 + tn * 8 + 2 * tg;
            size_t o0 = (size_t)r0 * PP + c, o1 = (size_t)r1 * PP + c;
            float2 dd0 = *(const float2*)(dist_in + o0);
            float2 dd1 = *(const float2*)(dist_in + o1);
            float* S = acc[tm][tn];
            float e00 = __expf(fminf(S[0]*isd - lam*dd0.x - td0, 11.f));
            float e01 = __expf(fminf(S[1]*isd - lam*dd0.y - td0, 11.f));
            float e10 = __expf(fminf(S[2]*isd - lam*dd1.x - td1, 11.f));
            float e11 = __expf(fminf(S[3]*isd - lam*dd1.y - td1, 11.f));
            s0 += e00 + e01;
            s1 += e10 + e11;
            *(uint32_t*)(g_Th + o0) = f2h2(e00, e01);
            *(uint32_t*)(g_Th + o1) = f2h2(e10, e11);
        }
        rs[tm][0] = s0; rs[tm][1] = s1;
    }
    #pragma unroll
    for (int tm = 0; tm < 2; tm++) {
        #pragma unroll
        for (int h = 0; h < 2; h++) {
            float s = rs[tm][h];
            s += __shfl_xor_sync(0xffffffffu, s, 1);
            s += __shfl_xor_sync(0xffffffffu, s, 2);
            if (tg == 0) ps[wm * 32 + tm * 16 + gr + h * 8][wn] = s;
        }
    }
    __syncthreads();
    if (tid < 128)
        g_psum[(size_t)(rowBase + tid) * 64 + blockIdx.x] = ps[tid][0] + ps[tid][1];
}

// ============================================================
// Kernel 6: g_inv[row] = 1 / sum over 64 col-tile partials
// ============================================================
__global__ void rowsum_kernel()
{
    int row = blockIdx.x, lane = threadIdx.x;  // 32 threads
    const float* p = g_psum + (size_t)row * 64;
    float s = p[lane] + p[lane + 32];
    #pragma unroll
    for (int o = 16; o > 0; o >>= 1) s += __shfl_xor_sync(0xffffffffu, s, o);
    if (lane == 0) g_inv[row] = 1.f / s;
}

// ============================================================
// Kernel 7: F_out = (E @ V) * (1/sum). fp16 mma, cp.async 4-stage.
// ============================================================
__device__ __forceinline__ void av_issue(uint32_t sbase, int stg, int kb, int tid,
    const __half* Ab, const __half* Bb)
{
    int row = tid >> 1;
    int ch0 = (tid & 1) * 2;
    uint32_t so = sbase + stg * 16384;
    size_t off = (size_t)row * PP + kb + ch0 * 8;
    cpa16(so +        swz64(row, ch0),     Ab + off);
    cpa16(so +        swz64(row, ch0 + 1), Ab + off + 8);
    cpa16(so + 8192 + swz64(row, ch0),     Bb + off);
    cpa16(so + 8192 + swz64(row, ch0 + 1), Bb + off + 8);
}

__global__ __launch_bounds__(256, 2) void av_e(float* __restrict__ out)
{
    extern __shared__ char dsm[];
    const uint32_t sbase = s2u(dsm);
    const int tid = threadIdx.x, lane = tid & 31, wid = tid >> 5;
    const int wm = wid & 3, wn = wid >> 2;
    const int rowBase = blockIdx.y * 128, colBase = blockIdx.x * 128;

    float acc[2][8][4] = {};

    const __half* Ab = g_Th  + (size_t)rowBase * PP;
    const __half* Bb = g_Vth + (size_t)colBase * PP;

    const int NKB = PP / 32;   // 256
    #pragma unroll
    for (int s = 0; s < 3; s++) {
        av_issue(sbase, s, s * 32, tid, Ab, Bb);
        cp_commit();
    }

    for (int kb = 0; kb < NKB; kb++) {
        cp_wait<2>();
        __syncthreads();
        if (kb + 3 < NKB)
            av_issue(sbase, (kb + 3) & 3, (kb + 3) * 32, tid, Ab, Bb);
        cp_commit();

        uint32_t su = sbase + (kb & 3) * 16384;
        #pragma unroll
        for (int ks = 0; ks < 2; ks++) {
            uint32_t a[2][4];
            fragA(su, wm * 32,      ks, lane, a[0]);
            fragA(su, wm * 32 + 16, ks, lane, a[1]);
            #pragma unroll
            for (int p = 0; p < 4; p++) {
                uint32_t b[4];
                fragB(su + 8192, wn * 64 + p * 16, ks, lane, b);
                #pragma unroll
                for (int tm = 0; tm < 2; tm++) {
                    mma16(acc[tm][2*p],   a[tm], b);
                    mma16(acc[tm][2*p+1], a[tm], b + 2);
                }
            }
        }
    }

    const int gr = lane >> 2, tg = lane & 3;
    #pragma unroll
    for (int tm = 0; tm < 2; tm++) {
        int r0 = rowBase + wm * 32 + tm * 16 + gr, r1 = r0 + 8;
        float i0 = g_inv[r0], i1 = g_inv[r1];
        #pragma unroll
        for (int tn = 0; tn < 8; tn++) {
            int c = colBase + wn * 64 + tn * 8 + 2 * tg;
            float* A = acc[tm][tn];
            *(float2*)(out + (size_t)r0 * DDIM + c) = make_float2(A[0]*i0, A[1]*i0);
            *(float2*)(out + (size_t)r1 * DDIM + c) = make_float2(A[2]*i1, A[3]*i1);
        }
    }
}

// ============================================================
extern "C" void kernel_launch(void* const* d_in, const int* in_sizes, int n_in,
                              void* d_out, int out_size)
{
    const float* F   = (const float*)d_in[0];
    const float* Wq  = (const float*)d_in[1];
    const float* bq  = (const float*)d_in[2];
    const float* Wk  = (const float*)d_in[3];
    const float* bk  = (const float*)d_in[4];
    const float* Wv  = (const float*)d_in[5];
    const float* bv  = (const float*)d_in[6];
    const float* lam = (const float*)d_in[7];

    float* out  = (float*)d_out;
    float* Fout = out;                        // [P, D]
    float* dist = out + (size_t)PP * DDIM;    // [P, P]

    static bool attr_done = false;
    if (!attr_done) {
        cudaFuncSetAttribute(dist_sym, cudaFuncAttributeMaxDynamicSharedMemorySize, 69632);
        cudaFuncSetAttribute(logits_s, cudaFuncAttributeMaxDynamicSharedMemorySize, 65536);
        cudaFuncSetAttribute(av_e,     cudaFuncAttributeMaxDynamicSharedMemorySize, 65536);
        attr_done = true;
    }

    norm_cvt_kernel<<<PP, 128>>>(F);
    qkv_h<<<dim3(DDIM/64, PP/128), 256>>>(Wq, bq, Wk, bk, Wv, bv);
    diag_kernel<<<PP, 128>>>();
    dist_sym<<<dim3(PP/128, PP/128), 256, 69632>>>(dist);
    logits_s<<<dim3(PP/128, PP/128), 256, 65536>>>(lam, dist);
    rowsum_kernel<<<PP, 32>>>();
    av_e<<<dim3(DDIM/128, PP/128), 256, 65536>>>(Fout);
}

// round 15
// speedup vs baseline: 2.2270x; 2.2270x over previous
#include <cuda_runtime.h>
#include <cuda_fp16.h>
#include <math.h>
#include <stdint.h>

#define PP 8192
#define DDIM 512
#define NT 64   // number of 128-wide tiles per dimension

// ---- scratch (device globals) ----
__device__ __half g_Qh[PP * DDIM];
__device__ __half g_Kh[PP * DDIM];
__device__ __half g_Fh[PP * DDIM];
__device__ __half g_Vth[DDIM * PP];          // V transposed: [feature][position]
__device__ __half g_Th[(size_t)PP * PP];     // unnormalized exp probs (fp16), 128 MB
__device__ float  g_psum[(size_t)PP * NT];   // per (row, colTile) partial sums
__device__ float  g_norm[PP];
__device__ float  g_tdiag[PP];
__device__ float  g_inv[PP];
__device__ float  g_qnorm[PP];
__device__ float  g_knorm[PP];
__device__ float  g_Qmax[NT];
__device__ float  g_Kmax[NT];
__device__ float  g_tdmin[NT];
__device__ float  g_dmin[NT * NT];
__device__ unsigned char g_skip[NT * NT];

// ---------------- helpers ----------------
__device__ __forceinline__ uint32_t s2u(const void* p) {
    return (uint32_t)__cvta_generic_to_shared(p);
}
__device__ __forceinline__ uint32_t f2h2(float a, float b) {
    __half2 h = __floats2half2_rn(a, b);
    return *reinterpret_cast<uint32_t*>(&h);
}
// tile rows of 32 halves (64B), 16B chunks XOR-swizzled
__device__ __forceinline__ int swz64(int r, int c) {
    return r * 64 + ((c ^ ((r >> 1) & 3)) << 4);
}
__device__ __forceinline__ void mma16(float* d, const uint32_t* a, const uint32_t* b) {
    asm volatile(
        "mma.sync.aligned.m16n8k16.row.col.f32.f16.f16.f32 "
        "{%0,%1,%2,%3},{%4,%5,%6,%7},{%8,%9},{%0,%1,%2,%3};"
        : "+f"(d[0]), "+f"(d[1]), "+f"(d[2]), "+f"(d[3])
        : "r"(a[0]), "r"(a[1]), "r"(a[2]), "r"(a[3]), "r"(b[0]), "r"(b[1]));
}
__device__ __forceinline__ void ldsm4(uint32_t addr, uint32_t* r) {
    asm volatile("ldmatrix.sync.aligned.m8n8.x4.shared.b16 {%0,%1,%2,%3}, [%4];"
        : "=r"(r[0]), "=r"(r[1]), "=r"(r[2]), "=r"(r[3]) : "r"(addr));
}
__device__ __forceinline__ void fragA(uint32_t tbase, int R, int ks, int lane, uint32_t* a) {
    int mi = lane >> 3, ri = lane & 7;
    int r = R + ri + (mi & 1) * 8;
    int c = ks * 2 + (mi >> 1);
    ldsm4(tbase + swz64(r, c), a);
}
__device__ __forceinline__ void fragB(uint32_t tbase, int N0, int ks, int lane, uint32_t* b) {
    int mi = lane >> 3, ri = lane & 7;
    int r = N0 + ri + (mi >> 1) * 8;
    int c = ks * 2 + (mi & 1);
    ldsm4(tbase + swz64(r, c), b);
}
// ---- cp.async ----
__device__ __forceinline__ void cpa16(uint32_t dst, const void* src) {
    asm volatile("cp.async.cg.shared.global [%0], [%1], 16;" :: "r"(dst), "l"(src));
}
__device__ __forceinline__ void cp_commit() {
    asm volatile("cp.async.commit_group;" ::: "memory");
}
template<int N>
__device__ __forceinline__ void cp_wait() {
    asm volatile("cp.async.wait_group %0;" :: "n"(N) : "memory");
}

// ------- reg-staged tiles for qkv -------
struct U8 { uint4 a, b; };
__device__ __forceinline__ U8 ldgH(const __half* g, size_t ld, int kb, int tid) {
    int row = tid >> 1, c0 = (tid & 1) * 16;
    const __half* p = g + (size_t)row * ld + kb + c0;
    U8 r; r.a = *(const uint4*)p; r.b = *(const uint4*)(p + 8);
    return r;
}
__device__ __forceinline__ void stsH(char* tile, U8 s, int tid) {
    int row = tid >> 1, c0 = (tid & 1) * 2;
    *(uint4*)(tile + swz64(row, c0))     = s.a;
    *(uint4*)(tile + swz64(row, c0 + 1)) = s.b;
}
struct W8 { float4 a, b; };
__device__ __forceinline__ W8 ldgW(const float* g, int ld, int kb, int tid) {
    int row = tid >> 2, c = tid & 3;
    const float* p = g + (size_t)row * ld + kb + c * 8;
    W8 r; r.a = *(const float4*)p; r.b = *(const float4*)(p + 4);
    return r;
}
__device__ __forceinline__ void stsW(char* tile, W8 s, int tid) {
    int row = tid >> 2, c = tid & 3;
    uint4 h;
    h.x = f2h2(s.a.x, s.a.y); h.y = f2h2(s.a.z, s.a.w);
    h.z = f2h2(s.b.x, s.b.y); h.w = f2h2(s.b.z, s.b.w);
    *(uint4*)(tile + swz64(row, c)) = h;
}

// ============================================================
// Kernel 1: row norms of F + convert F -> g_Fh
// ============================================================
__global__ void norm_cvt_kernel(const float* __restrict__ F)
{
    int row = blockIdx.x, tid = threadIdx.x;   // 128 threads
    const float4* fr = (const float4*)(F + (size_t)row * DDIM);
    float4 v = fr[tid];
    float s = v.x*v.x + v.y*v.y + v.z*v.z + v.w*v.w;
    uint2 h; h.x = f2h2(v.x, v.y); h.y = f2h2(v.z, v.w);
    *(uint2*)(g_Fh + (size_t)row * DDIM + tid * 4) = h;
    #pragma unroll
    for (int o = 16; o > 0; o >>= 1) s += __shfl_xor_sync(0xffffffffu, s, o);
    __shared__ float red[4];
    if ((tid & 31) == 0) red[tid >> 5] = s;
    __syncthreads();
    if (tid == 0) g_norm[row] = red[0] + red[1] + red[2] + red[3];
}

// ============================================================
// Kernel 2: Q/K/V = F @ W^T + b (fp16 mma). Outputs Qh,Kh,Vth.
// ============================================================
__global__ __launch_bounds__(256) void qkv_h(
    const float* __restrict__ Wq, const float* __restrict__ bq,
    const float* __restrict__ Wk, const float* __restrict__ bk,
    const float* __restrict__ Wv, const float* __restrict__ bv)
{
    __shared__ char smem[2 * 20 * 1024];
    const int tid = threadIdx.x, lane = tid & 31, wid = tid >> 5;
    const int wm = wid & 3, wn = wid >> 2;
    const int rowBase = blockIdx.y * 128, colBase = blockIdx.x * 64;

    float aq[2][4][4] = {}, ak[2][4][4] = {}, avv[2][4][4] = {};

    const __half* Fb = g_Fh + (size_t)rowBase * DDIM;
    const float* Qb = Wq + (size_t)colBase * DDIM;
    const float* Kb = Wk + (size_t)colBase * DDIM;
    const float* Vb = Wv + (size_t)colBase * DDIM;

    U8 pf = ldgH(Fb, DDIM, 0, tid);
    W8 pq = ldgW(Qb, DDIM, 0, tid);
    W8 pk = ldgW(Kb, DDIM, 0, tid);
    W8 pv = ldgW(Vb, DDIM, 0, tid);
    char* buf0 = smem; char* buf1 = smem + 20 * 1024;
    stsH(buf0, pf, tid);
    stsW(buf0 +  8192, pq, tid);
    stsW(buf0 + 12288, pk, tid);
    stsW(buf0 + 16384, pv, tid);
    __syncthreads();

    const int NKB = DDIM / 32;   // 16
    for (int kb = 0; kb < NKB; kb++) {
        if (kb + 1 < NKB) {
            int k = (kb + 1) * 32;
            pf = ldgH(Fb, DDIM, k, tid);
            pq = ldgW(Qb, DDIM, k, tid);
            pk = ldgW(Kb, DDIM, k, tid);
            pv = ldgW(Vb, DDIM, k, tid);
        }
        uint32_t su = s2u((kb & 1) ? buf1 : buf0);
        #pragma unroll
        for (int ks = 0; ks < 2; ks++) {
            uint32_t a[2][4];
            fragA(su, wm * 32,      ks, lane, a[0]);
            fragA(su, wm * 32 + 16, ks, lane, a[1]);
            #pragma unroll
            for (int p = 0; p < 2; p++) {
                uint32_t b[4];
                fragB(su + 8192, wn * 32 + p * 16, ks, lane, b);
                #pragma unroll
                for (int tm = 0; tm < 2; tm++) {
                    mma16(aq[tm][2*p],   a[tm], b);
                    mma16(aq[tm][2*p+1], a[tm], b + 2);
                }
                fragB(su + 12288, wn * 32 + p * 16, ks, lane, b);
                #pragma unroll
                for (int tm = 0; tm < 2; tm++) {
                    mma16(ak[tm][2*p],   a[tm], b);
                    mma16(ak[tm][2*p+1], a[tm], b + 2);
                }
                fragB(su + 16384, wn * 32 + p * 16, ks, lane, b);
                #pragma unroll
                for (int tm = 0; tm < 2; tm++) {
                    mma16(avv[tm][2*p],   a[tm], b);
                    mma16(avv[tm][2*p+1], a[tm], b + 2);
                }
            }
        }
        char* nxt = (kb & 1) ? buf0 : buf1;
        if (kb + 1 < NKB) {
            stsH(nxt, pf, tid);
            stsW(nxt +  8192, pq, tid);
            stsW(nxt + 12288, pk, tid);
            stsW(nxt + 16384, pv, tid);
        }
        __syncthreads();
    }

    const int gr = lane >> 2, tg = lane & 3;
    #pragma unroll
    for (int tm = 0; tm < 2; tm++) {
        int r0 = rowBase + wm * 32 + tm * 16 + gr, r1 = r0 + 8;
        #pragma unroll
        for (int tn = 0; tn < 4; tn++) {
            int c = colBase + wn * 32 + tn * 8 + 2 * tg;
            float bq0 = bq[c], bq1 = bq[c+1];
            float bk0 = bk[c], bk1 = bk[c+1];
            float bv0 = bv[c], bv1 = bv[c+1];
            float* A = aq[tm][tn];
            *(uint32_t*)(g_Qh + (size_t)r0 * DDIM + c) = f2h2(A[0] + bq0, A[1] + bq1);
            *(uint32_t*)(g_Qh + (size_t)r1 * DDIM + c) = f2h2(A[2] + bq0, A[3] + bq1);
            A = ak[tm][tn];
            *(uint32_t*)(g_Kh + (size_t)r0 * DDIM + c) = f2h2(A[0] + bk0, A[1] + bk1);
            *(uint32_t*)(g_Kh + (size_t)r1 * DDIM + c) = f2h2(A[2] + bk0, A[3] + bk1);
            A = avv[tm][tn];
            g_Vth[(size_t)c     * PP + r0] = __float2half(A[0] + bv0);
            g_Vth[(size_t)(c+1) * PP + r0] = __float2half(A[1] + bv1);
            g_Vth[(size_t)c     * PP + r1] = __float2half(A[2] + bv0);
            g_Vth[(size_t)(c+1) * PP + r1] = __float2half(A[3] + bv1);
        }
    }
}

// ============================================================
// Kernel 3: tdiag[i] = (Q_i.K_i)/sqrt(d); also |Q_i|, |K_i| norms.
// ============================================================
__global__ void diag_kernel()
{
    int row = blockIdx.x, tid = threadIdx.x;   // 128 threads
    const __half* Q = g_Qh + (size_t)row * DDIM + tid * 4;
    const __half* K = g_Kh + (size_t)row * DDIM + tid * 4;
    uint2 qa = *(const uint2*)Q;
    uint2 ka = *(const uint2*)K;
    __half2 q0 = *(__half2*)&qa.x, q1 = *(__half2*)&qa.y;
    __half2 k0 = *(__half2*)&ka.x, k1 = *(__half2*)&ka.y;
    float2 qf0 = __half22float2(q0), qf1 = __half22float2(q1);
    float2 kf0 = __half22float2(k0), kf1 = __half22float2(k1);
    float s  = qf0.x*kf0.x + qf0.y*kf0.y + qf1.x*kf1.x + qf1.y*kf1.y;
    float qq = qf0.x*qf0.x + qf0.y*qf0.y + qf1.x*qf1.x + qf1.y*qf1.y;
    float kk = kf0.x*kf0.x + kf0.y*kf0.y + kf1.x*kf1.x + kf1.y*kf1.y;
    #pragma unroll
    for (int o = 16; o > 0; o >>= 1) {
        s  += __shfl_xor_sync(0xffffffffu, s, o);
        qq += __shfl_xor_sync(0xffffffffu, qq, o);
        kk += __shfl_xor_sync(0xffffffffu, kk, o);
    }
    __shared__ float rs[4], rq[4], rk[4];
    if ((tid & 31) == 0) { rs[tid >> 5] = s; rq[tid >> 5] = qq; rk[tid >> 5] = kk; }
    __syncthreads();
    if (tid == 0) {
        g_tdiag[row] = (rs[0] + rs[1] + rs[2] + rs[3]) * 0.044194173824159216f;
        g_qnorm[row] = sqrtf(rq[0] + rq[1] + rq[2] + rq[3]);
        g_knorm[row] = sqrtf(rk[0] + rk[1] + rk[2] + rk[3]);
    }
}

// ============================================================
// Kernel 3b: per-tile stats (max |Q|, max |K|, min tdiag)
// ============================================================
__global__ void tilestat_kernel()
{
    int b = blockIdx.x, tid = threadIdx.x;   // 128 threads
    int row = b * 128 + tid;
    float q = g_qnorm[row], k = g_knorm[row], t = g_tdiag[row];
    #pragma unroll
    for (int o = 16; o > 0; o >>= 1) {
        q = fmaxf(q, __shfl_xor_sync(0xffffffffu, q, o));
        k = fmaxf(k, __shfl_xor_sync(0xffffffffu, k, o));
        t = fminf(t, __shfl_xor_sync(0xffffffffu, t, o));
    }
    __shared__ float rq[4], rk[4], rt[4];
    if ((tid & 31) == 0) { rq[tid >> 5] = q; rk[tid >> 5] = k; rt[tid >> 5] = t; }
    __syncthreads();
    if (tid == 0) {
        g_Qmax[b]  = fmaxf(fmaxf(rq[0], rq[1]), fmaxf(rq[2], rq[3]));
        g_Kmax[b]  = fmaxf(fmaxf(rk[0], rk[1]), fmaxf(rk[2], rk[3]));
        g_tdmin[b] = fminf(fminf(rt[0], rt[1]), fminf(rt[2], rt[3]));
    }
}

// ============================================================
// Kernel 4: dist via G=FF^T, triangular-packed grid (2080 CTAs).
// Writes dist direct + mirrored; per-tile min dist -> g_dmin (both).
// ============================================================
__device__ __forceinline__ void ds_issue(uint32_t sbase, int stg, int kb, int tid,
    const __half* Fr, const __half* Fc)
{
    int row = tid >> 1;
    int ch0 = (tid & 1) * 2;
    uint32_t so = sbase + stg * 16384;
    size_t off = (size_t)row * DDIM + kb + ch0 * 8;
    cpa16(so +        swz64(row, ch0),     Fr + off);
    cpa16(so +        swz64(row, ch0 + 1), Fr + off + 8);
    cpa16(so + 8192 + swz64(row, ch0),     Fc + off);
    cpa16(so + 8192 + swz64(row, ch0 + 1), Fc + off + 8);
}

__global__ __launch_bounds__(256, 2) void dist_sym(float* __restrict__ dist_out)
{
    // triangular decode: t -> (bx <= by)
    int t = blockIdx.x;
    int by = (int)((sqrtf(8.f * t + 1.f) - 1.f) * 0.5f);
    while ((by + 1) * (by + 2) / 2 <= t) by++;
    while (by * (by + 1) / 2 > t) by--;
    int bx = t - by * (by + 1) / 2;

    extern __shared__ char dsm[];
    __shared__ float dmn[8];
    const uint32_t sbase = s2u(dsm);
    const int tid = threadIdx.x, lane = tid & 31, wid = tid >> 5;
    const int wm = wid & 3, wn = wid >> 2;
    const int rowBase = by * 128, colBase = bx * 128;

    float acc[2][8][4] = {};

    const __half* Fr = g_Fh + (size_t)rowBase * DDIM;
    const __half* Fc = g_Fh + (size_t)colBase * DDIM;

    const int NKB = DDIM / 32;   // 16
    #pragma unroll
    for (int s = 0; s < 3; s++) {
        ds_issue(sbase, s, s * 32, tid, Fr, Fc);
        cp_commit();
    }

    for (int kb = 0; kb < NKB; kb++) {
        cp_wait<2>();
        __syncthreads();
        if (kb + 3 < NKB)
            ds_issue(sbase, (kb + 3) & 3, (kb + 3) * 32, tid, Fr, Fc);
        cp_commit();

        uint32_t su = sbase + (kb & 3) * 16384;
        #pragma unroll
        for (int ks = 0; ks < 2; ks++) {
            uint32_t a[2][4];
            fragA(su, wm * 32,      ks, lane, a[0]);
            fragA(su, wm * 32 + 16, ks, lane, a[1]);
            #pragma unroll
            for (int p = 0; p < 4; p++) {
                uint32_t b[4];
                fragB(su + 8192, wn * 64 + p * 16, ks, lane, b);
                #pragma unroll
                for (int tm = 0; tm < 2; tm++) {
                    mma16(acc[tm][2*p],   a[tm], b);
                    mma16(acc[tm][2*p+1], a[tm], b + 2);
                }
            }
        }
    }
    cp_wait<0>();
    __syncthreads();

    // epilogue: dist = sqrt(max(nr + nc - 2G, 0)); direct + transpose; track min
    float* st = (float*)dsm;   // [128][132] floats
    const int gr = lane >> 2, tg = lane & 3;
    float locmin = 3.4e38f;
    #pragma unroll
    for (int tm = 0; tm < 2; tm++) {
        int rl0 = wm * 32 + tm * 16 + gr, rl1 = rl0 + 8;
        int r0 = rowBase + rl0, r1 = rowBase + rl1;
        float n0 = g_norm[r0], n1 = g_norm[r1];
        #pragma unroll
        for (int tn = 0; tn < 8; tn++) {
            int cl = wn * 64 + tn * 8 + 2 * tg;
            int c = colBase + cl;
            float nc0 = g_norm[c], nc1 = g_norm[c+1];
            float* A = acc[tm][tn];
            float d00 = sqrtf(fmaxf(n0 + nc0 - 2.f * A[0], 0.f));
            float d01 = sqrtf(fmaxf(n0 + nc1 - 2.f * A[1], 0.f));
            float d10 = sqrtf(fmaxf(n1 + nc0 - 2.f * A[2], 0.f));
            float d11 = sqrtf(fmaxf(n1 + nc1 - 2.f * A[3], 0.f));
            locmin = fminf(locmin, fminf(fminf(d00, d01), fminf(d10, d11)));
            *(float2*)(dist_out + (size_t)r0 * PP + c) = make_float2(d00, d01);
            *(float2*)(dist_out + (size_t)r1 * PP + c) = make_float2(d10, d11);
            st[(cl    ) * 132 + rl0] = d00;
            st[(cl + 1) * 132 + rl0] = d01;
            st[(cl    ) * 132 + rl1] = d10;
            st[(cl + 1) * 132 + rl1] = d11;
        }
    }
    #pragma unroll
    for (int o = 16; o > 0; o >>= 1) locmin = fminf(locmin, __shfl_xor_sync(0xffffffffu, locmin, o));
    if (lane == 0) dmn[wid] = locmin;
    __syncthreads();
    if (tid == 0) {
        float m = dmn[0];
        #pragma unroll
        for (int w = 1; w < 8; w++) m = fminf(m, dmn[w]);
        g_dmin[by * NT + bx] = m;
        g_dmin[bx * NT + by] = m;
    }
    if (bx != by) {
        int i = tid >> 1;
        int j0 = (tid & 1) * 64;
        const float* srow = st + i * 132 + j0;
        float* orow = dist_out + (size_t)(colBase + i) * PP + rowBase + j0;
        #pragma unroll
        for (int j = 0; j < 64; j += 4)
            *(float4*)(orow + j) = *(const float4*)(srow + j);
    }
}

// ============================================================
// Kernel 5: S=QK^T with provable tile skipping.
// If isd*Qmax*Kmax - tdmin - lam*dmin < -20, every E in the tile
// rounds to fp16 zero -> skip (write psum=0 + flag).
// ============================================================
__device__ __forceinline__ void ls_issue(uint32_t sbase, int stg, int kb, int tid,
    const __half* Qb, const __half* Kb)
{
    int row = tid >> 1;
    int ch0 = (tid & 1) * 2;
    uint32_t so = sbase + stg * 16384;
    size_t off = (size_t)row * DDIM + kb + ch0 * 8;
    cpa16(so +        swz64(row, ch0),     Qb + off);
    cpa16(so +        swz64(row, ch0 + 1), Qb + off + 8);
    cpa16(so + 8192 + swz64(row, ch0),     Kb + off);
    cpa16(so + 8192 + swz64(row, ch0 + 1), Kb + off + 8);
}

__global__ __launch_bounds__(256, 2) void logits_s(
    const float* __restrict__ lamP, const float* __restrict__ dist_in)
{
    const int bx = blockIdx.x, by = blockIdx.y;
    const int tid = threadIdx.x;
    const float lam = *lamP;
    const float isd = 0.044194173824159216f;  // 1/sqrt(512)

    float bound = isd * g_Qmax[by] * g_Kmax[bx] - g_tdmin[by] - lam * g_dmin[by * NT + bx];
    if (bound < -20.f) {
        if (tid == 0) g_skip[by * NT + bx] = 1;
        if (tid < 128) g_psum[(size_t)(by * 128 + tid) * NT + bx] = 0.f;
        return;
    }
    if (tid == 0) g_skip[by * NT + bx] = 0;

    extern __shared__ char dsm[];
    __shared__ float ps[128][2];
    const uint32_t sbase = s2u(dsm);
    const int lane = tid & 31, wid = tid >> 5;
    const int wm = wid & 3, wn = wid >> 2;
    const int rowBase = by * 128, colBase = bx * 128;

    float acc[2][8][4] = {};

    const __half* Qb = g_Qh + (size_t)rowBase * DDIM;
    const __half* Kb = g_Kh + (size_t)colBase * DDIM;

    const int NKB = DDIM / 32;   // 16
    #pragma unroll
    for (int s = 0; s < 3; s++) {
        ls_issue(sbase, s, s * 32, tid, Qb, Kb);
        cp_commit();
    }

    for (int kb = 0; kb < NKB; kb++) {
        cp_wait<2>();
        __syncthreads();
        if (kb + 3 < NKB)
            ls_issue(sbase, (kb + 3) & 3, (kb + 3) * 32, tid, Qb, Kb);
        cp_commit();

        uint32_t su = sbase + (kb & 3) * 16384;
        #pragma unroll
        for (int ks = 0; ks < 2; ks++) {
            uint32_t a[2][4];
            fragA(su, wm * 32,      ks, lane, a[0]);
            fragA(su, wm * 32 + 16, ks, lane, a[1]);
            #pragma unroll
            for (int p = 0; p < 4; p++) {
                uint32_t b[4];
                fragB(su + 8192, wn * 64 + p * 16, ks, lane, b);
                #pragma unroll
                for (int tm = 0; tm < 2; tm++) {
                    mma16(acc[tm][2*p],   a[tm], b);
                    mma16(acc[tm][2*p+1], a[tm], b + 2);
                }
            }
        }
    }

    const int gr = lane >> 2, tg = lane & 3;
    float rs[2][2];
    #pragma unroll
    for (int tm = 0; tm < 2; tm++) {
        int r0 = rowBase + wm * 32 + tm * 16 + gr, r1 = r0 + 8;
        float td0 = g_tdiag[r0], td1 = g_tdiag[r1];
        float s0 = 0.f, s1 = 0.f;
        #pragma unroll
        for (int tn = 0; tn < 8; tn++) {
            int c = colBase + wn * 64 + tn * 8 + 2 * tg;
            size_t o0 = (size_t)r0 * PP + c, o1 = (size_t)r1 * PP + c;
            float2 dd0 = *(const float2*)(dist_in + o0);
            float2 dd1 = *(const float2*)(dist_in + o1);
            float* S = acc[tm][tn];
            float e00 = __expf(fminf(S[0]*isd - lam*dd0.x - td0, 11.f));
            float e01 = __expf(fminf(S[1]*isd - lam*dd0.y - td0, 11.f));
            float e10 = __expf(fminf(S[2]*isd - lam*dd1.x - td1, 11.f));
            float e11 = __expf(fminf(S[3]*isd - lam*dd1.y - td1, 11.f));
            s0 += e00 + e01;
            s1 += e10 + e11;
            *(uint32_t*)(g_Th + o0) = f2h2(e00, e01);
            *(uint32_t*)(g_Th + o1) = f2h2(e10, e11);
        }
        rs[tm][0] = s0; rs[tm][1] = s1;
    }
    #pragma unroll
    for (int tm = 0; tm < 2; tm++) {
        #pragma unroll
        for (int h = 0; h < 2; h++) {
            float s = rs[tm][h];
            s += __shfl_xor_sync(0xffffffffu, s, 1);
            s += __shfl_xor_sync(0xffffffffu, s, 2);
            if (tg == 0) ps[wm * 32 + tm * 16 + gr + h * 8][wn] = s;
        }
    }
    __syncthreads();
    if (tid < 128)
        g_psum[(size_t)(rowBase + tid) * NT + bx] = ps[tid][0] + ps[tid][1];
}

// ============================================================
// Kernel 6: g_inv[row] = 1 / sum over 64 col-tile partials
// ============================================================
__global__ void rowsum_kernel()
{
    int row = blockIdx.x, lane = threadIdx.x;  // 32 threads
    const float* p = g_psum + (size_t)row * NT;
    float s = p[lane] + p[lane + 32];
    #pragma unroll
    for (int o = 16; o > 0; o >>= 1) s += __shfl_xor_sync(0xffffffffu, s, o);
    if (lane == 0) g_inv[row] = 1.f / s;
}

// ============================================================
// Kernel 7: F_out = (E @ V) * (1/sum). Skips all-zero col-tiles.
// ============================================================
__device__ __forceinline__ void av_issue(uint32_t sbase, int stg, int kOff, int tid,
    const __half* Ab, const __half* Bb)
{
    int row = tid >> 1;
    int ch0 = (tid & 1) * 2;
    uint32_t so = sbase + stg * 16384;
    size_t off = (size_t)row * PP + kOff + ch0 * 8;
    cpa16(so +        swz64(row, ch0),     Ab + off);
    cpa16(so +        swz64(row, ch0 + 1), Ab + off + 8);
    cpa16(so + 8192 + swz64(row, ch0),     Bb + off);
    cpa16(so + 8192 + swz64(row, ch0 + 1), Bb + off + 8);
}

__global__ __launch_bounds__(256, 2) void av_e(float* __restrict__ out)
{
    extern __shared__ char dsm[];
    __shared__ int act[NT];
    __shared__ int nactS;
    const uint32_t sbase = s2u(dsm);
    const int tid = threadIdx.x, lane = tid & 31, wid = tid >> 5;
    const int wm = wid & 3, wn = wid >> 2;
    const int rowBase = blockIdx.y * 128, colBase = blockIdx.x * 128;
    const int ry = blockIdx.y;

    if (tid == 0) {
        int n = 0;
        for (int ct = 0; ct < NT; ct++)
            if (!g_skip[ry * NT + ct]) act[n++] = ct;
        nactS = n;
    }
    __syncthreads();
    const int nch = nactS * 4;   // 4 k-chunks of 32 per active col-tile

    float acc[2][8][4] = {};

    const __half* Ab = g_Th  + (size_t)rowBase * PP;
    const __half* Bb = g_Vth + (size_t)colBase * PP;

    #pragma unroll
    for (int s = 0; s < 3; s++) {
        if (s < nch) av_issue(sbase, s, act[s >> 2] * 128 + (s & 3) * 32, tid, Ab, Bb);
        cp_commit();
    }

    for (int i = 0; i < nch; i++) {
        cp_wait<2>();
        __syncthreads();
        if (i + 3 < nch) {
            int j = i + 3;
            av_issue(sbase, j & 3, act[j >> 2] * 128 + (j & 3) * 32, tid, Ab, Bb);
        }
        cp_commit();

        uint32_t su = sbase + (i & 3) * 16384;
        #pragma unroll
        for (int ks = 0; ks < 2; ks++) {
            uint32_t a[2][4];
            fragA(su, wm * 32,      ks, lane, a[0]);
            fragA(su, wm * 32 + 16, ks, lane, a[1]);
            #pragma unroll
            for (int p = 0; p < 4; p++) {
                uint32_t b[4];
                fragB(su + 8192, wn * 64 + p * 16, ks, lane, b);
                #pragma unroll
                for (int tm = 0; tm < 2; tm++) {
                    mma16(acc[tm][2*p],   a[tm], b);
                    mma16(acc[tm][2*p+1], a[tm], b + 2);
                }
            }
        }
    }

    const int gr = lane >> 2, tg = lane & 3;
    #pragma unroll
    for (int tm = 0; tm < 2; tm++) {
        int r0 = rowBase + wm * 32 + tm * 16 + gr, r1 = r0 + 8;
        float i0 = g_inv[r0], i1 = g_inv[r1];
        #pragma unroll
        for (int tn = 0; tn < 8; tn++) {
            int c = colBase + wn * 64 + tn * 8 + 2 * tg;
            float* A = acc[tm][tn];
            *(float2*)(out + (size_t)r0 * DDIM + c) = make_float2(A[0]*i0, A[1]*i0);
            *(float2*)(out + (size_t)r1 * DDIM + c) = make_float2(A[2]*i1, A[3]*i1);
        }
    }
}

// ============================================================
extern "C" void kernel_launch(void* const* d_in, const int* in_sizes, int n_in,
                              void* d_out, int out_size)
{
    const float* F   = (const float*)d_in[0];
    const float* Wq  = (const float*)d_in[1];
    const float* bq  = (const float*)d_in[2];
    const float* Wk  = (const float*)d_in[3];
    const float* bk  = (const float*)d_in[4];
    const float* Wv  = (const float*)d_in[5];
    const float* bv  = (const float*)d_in[6];
    const float* lam = (const float*)d_in[7];

    float* out  = (float*)d_out;
    float* Fout = out;                        // [P, D]
    float* dist = out + (size_t)PP * DDIM;    // [P, P]

    static bool attr_done = false;
    if (!attr_done) {
        cudaFuncSetAttribute(dist_sym, cudaFuncAttributeMaxDynamicSharedMemorySize, 69632);
        cudaFuncSetAttribute(logits_s, cudaFuncAttributeMaxDynamicSharedMemorySize, 65536);
        cudaFuncSetAttribute(av_e,     cudaFuncAttributeMaxDynamicSharedMemorySize, 65536);
        attr_done = true;
    }

    norm_cvt_kernel<<<PP, 128>>>(F);
    qkv_h<<<dim3(DDIM/64, PP/128), 256>>>(Wq, bq, Wk, bk, Wv, bv);
    diag_kernel<<<PP, 128>>>();
    tilestat_kernel<<<NT, 128>>>();
    dist_sym<<<NT * (NT + 1) / 2, 256, 69632>>>(dist);
    logits_s<<<dim3(NT, NT), 256, 65536>>>(lam, dist);
    rowsum_kernel<<<PP, 32>>>();
    av_e<<<dim3(DDIM/128, PP/128), 256, 65536>>>(Fout);
}

// round 16
// speedup vs baseline: 2.3128x; 1.0385x over previous
#include <cuda_runtime.h>
#include <cuda_fp16.h>
#include <math.h>
#include <stdint.h>

#define PP 8192
#define DDIM 512
#define NT 64   // number of 128-wide tiles per dimension

// ---- scratch (device globals) ----
__device__ __half g_Qh[PP * DDIM];
__device__ __half g_Kh[PP * DDIM];
__device__ __half g_Fh[PP * DDIM];
__device__ __half g_Vh[PP * DDIM];           // V row-major [position][feature]
__device__ __half g_Vth[DDIM * PP];          // V transposed: [feature][position]
__device__ __half g_Wh[3 * DDIM * DDIM];     // fp16 weights: Wq, Wk, Wv
__device__ __half g_Th[(size_t)PP * PP];     // unnormalized exp probs (fp16), 128 MB
__device__ float  g_psum[(size_t)PP * NT];   // per (row, colTile) partial sums
__device__ float  g_norm[PP];
__device__ float  g_tdiag[PP];
__device__ float  g_inv[PP];
__device__ float  g_qnorm[PP];
__device__ float  g_knorm[PP];
__device__ float  g_Qmax[NT];
__device__ float  g_Kmax[NT];
__device__ float  g_tdmin[NT];
__device__ float  g_dmin[NT * NT];
__device__ unsigned char g_skip[NT * NT];

// ---------------- helpers ----------------
__device__ __forceinline__ uint32_t s2u(const void* p) {
    return (uint32_t)__cvta_generic_to_shared(p);
}
__device__ __forceinline__ uint32_t f2h2(float a, float b) {
    __half2 h = __floats2half2_rn(a, b);
    return *reinterpret_cast<uint32_t*>(&h);
}
// tile rows of 32 halves (64B), 16B chunks XOR-swizzled
__device__ __forceinline__ int swz64(int r, int c) {
    return r * 64 + ((c ^ ((r >> 1) & 3)) << 4);
}
__device__ __forceinline__ void mma16(float* d, const uint32_t* a, const uint32_t* b) {
    asm volatile(
        "mma.sync.aligned.m16n8k16.row.col.f32.f16.f16.f32 "
        "{%0,%1,%2,%3},{%4,%5,%6,%7},{%8,%9},{%0,%1,%2,%3};"
        : "+f"(d[0]), "+f"(d[1]), "+f"(d[2]), "+f"(d[3])
        : "r"(a[0]), "r"(a[1]), "r"(a[2]), "r"(a[3]), "r"(b[0]), "r"(b[1]));
}
__device__ __forceinline__ void ldsm4(uint32_t addr, uint32_t* r) {
    asm volatile("ldmatrix.sync.aligned.m8n8.x4.shared.b16 {%0,%1,%2,%3}, [%4];"
        : "=r"(r[0]), "=r"(r[1]), "=r"(r[2]), "=r"(r[3]) : "r"(addr));
}
__device__ __forceinline__ void fragA(uint32_t tbase, int R, int ks, int lane, uint32_t* a) {
    int mi = lane >> 3, ri = lane & 7;
    int r = R + ri + (mi & 1) * 8;
    int c = ks * 2 + (mi >> 1);
    ldsm4(tbase + swz64(r, c), a);
}
__device__ __forceinline__ void fragB(uint32_t tbase, int N0, int ks, int lane, uint32_t* b) {
    int mi = lane >> 3, ri = lane & 7;
    int r = N0 + ri + (mi >> 1) * 8;
    int c = ks * 2 + (mi & 1);
    ldsm4(tbase + swz64(r, c), b);
}
// ---- cp.async ----
__device__ __forceinline__ void cpa16(uint32_t dst, const void* src) {
    asm volatile("cp.async.cg.shared.global [%0], [%1], 16;" :: "r"(dst), "l"(src));
}
__device__ __forceinline__ void cp_commit() {
    asm volatile("cp.async.commit_group;" ::: "memory");
}
template<int N>
__device__ __forceinline__ void cp_wait() {
    asm volatile("cp.async.wait_group %0;" :: "n"(N) : "memory");
}

// ============================================================
// Kernel 0: convert weights to fp16 (same rounding as before)
// ============================================================
__global__ void wcvt_kernel(const float* __restrict__ Wq,
                            const float* __restrict__ Wk,
                            const float* __restrict__ Wv)
{
    const float* src = (blockIdx.y == 0) ? Wq : (blockIdx.y == 1) ? Wk : Wv;
    __half* dst = g_Wh + (size_t)blockIdx.y * DDIM * DDIM;
    int i = (blockIdx.x * 256 + threadIdx.x) * 4;
    float4 v = *(const float4*)(src + i);
    uint2 h; h.x = f2h2(v.x, v.y); h.y = f2h2(v.z, v.w);
    *(uint2*)(dst + i) = h;
}

// ============================================================
// Kernel 1: row norms of F + convert F -> g_Fh. Warp per row.
// ============================================================
__global__ __launch_bounds__(256) void norm_cvt_kernel(const float* __restrict__ F)
{
    int warp = threadIdx.x >> 5, lane = threadIdx.x & 31;
    int row = blockIdx.x * 8 + warp;
    const float4* fr = (const float4*)(F + (size_t)row * DDIM);
    __half* fh = g_Fh + (size_t)row * DDIM;
    float s = 0.f;
    #pragma unroll
    for (int i = 0; i < 4; i++) {
        float4 v = fr[lane + i * 32];
        s += v.x*v.x + v.y*v.y + v.z*v.z + v.w*v.w;
        uint2 h; h.x = f2h2(v.x, v.y); h.y = f2h2(v.z, v.w);
        *(uint2*)(fh + (lane + i * 32) * 4) = h;
    }
    #pragma unroll
    for (int o = 16; o > 0; o >>= 1) s += __shfl_xor_sync(0xffffffffu, s, o);
    if (lane == 0) g_norm[row] = s;
}

// ============================================================
// Kernel 2: Q/K/V = F @ W^T + b. All-fp16 cp.async 4-stage.
// Tile 128x64, 3 outputs. Q,K,V all written row-major coalesced.
// ============================================================
__device__ __forceinline__ void qk_issue(uint32_t sbase, int stg, int kb, int tid,
    const __half* Fb, const __half* W0, const __half* W1, const __half* W2)
{
    uint32_t so = sbase + stg * 20480;
    int row = tid >> 1, ch0 = (tid & 1) * 2;
    size_t offA = (size_t)row * DDIM + kb + ch0 * 8;
    cpa16(so + swz64(row, ch0),     Fb + offA);
    cpa16(so + swz64(row, ch0 + 1), Fb + offA + 8);
    int brow = tid >> 2, bch = tid & 3;
    size_t offB = (size_t)brow * DDIM + kb + bch * 8;
    cpa16(so +  8192 + swz64(brow, bch), W0 + offB);
    cpa16(so + 12288 + swz64(brow, bch), W1 + offB);
    cpa16(so + 16384 + swz64(brow, bch), W2 + offB);
}

__global__ __launch_bounds__(256, 2) void qkv_h(
    const float* __restrict__ bq, const float* __restrict__ bk,
    const float* __restrict__ bv)
{
    extern __shared__ char dsm[];
    const uint32_t sbase = s2u(dsm);
    const int tid = threadIdx.x, lane = tid & 31, wid = tid >> 5;
    const int wm = wid & 3, wn = wid >> 2;
    const int rowBase = blockIdx.y * 128, colBase = blockIdx.x * 64;

    float aq[2][4][4] = {}, ak[2][4][4] = {}, avv[2][4][4] = {};

    const __half* Fb = g_Fh + (size_t)rowBase * DDIM;
    const __half* W0 = g_Wh + (size_t)colBase * DDIM;
    const __half* W1 = g_Wh + (size_t)DDIM * DDIM     + (size_t)colBase * DDIM;
    const __half* W2 = g_Wh + (size_t)DDIM * DDIM * 2 + (size_t)colBase * DDIM;

    const int NKB = DDIM / 32;   // 16
    #pragma unroll
    for (int s = 0; s < 3; s++) {
        qk_issue(sbase, s, s * 32, tid, Fb, W0, W1, W2);
        cp_commit();
    }

    for (int kb = 0; kb < NKB; kb++) {
        cp_wait<2>();
        __syncthreads();
        if (kb + 3 < NKB)
            qk_issue(sbase, (kb + 3) & 3, (kb + 3) * 32, tid, Fb, W0, W1, W2);
        cp_commit();

        uint32_t su = sbase + (kb & 3) * 20480;
        #pragma unroll
        for (int ks = 0; ks < 2; ks++) {
            uint32_t a[2][4];
            fragA(su, wm * 32,      ks, lane, a[0]);
            fragA(su, wm * 32 + 16, ks, lane, a[1]);
            #pragma unroll
            for (int p = 0; p < 2; p++) {
                uint32_t b[4];
                fragB(su + 8192, wn * 32 + p * 16, ks, lane, b);
                #pragma unroll
                for (int tm = 0; tm < 2; tm++) {
                    mma16(aq[tm][2*p],   a[tm], b);
                    mma16(aq[tm][2*p+1], a[tm], b + 2);
                }
                fragB(su + 12288, wn * 32 + p * 16, ks, lane, b);
                #pragma unroll
                for (int tm = 0; tm < 2; tm++) {
                    mma16(ak[tm][2*p],   a[tm], b);
                    mma16(ak[tm][2*p+1], a[tm], b + 2);
                }
                fragB(su + 16384, wn * 32 + p * 16, ks, lane, b);
                #pragma unroll
                for (int tm = 0; tm < 2; tm++) {
                    mma16(avv[tm][2*p],   a[tm], b);
                    mma16(avv[tm][2*p+1], a[tm], b + 2);
                }
            }
        }
    }

    const int gr = lane >> 2, tg = lane & 3;
    #pragma unroll
    for (int tm = 0; tm < 2; tm++) {
        int r0 = rowBase + wm * 32 + tm * 16 + gr, r1 = r0 + 8;
        #pragma unroll
        for (int tn = 0; tn < 4; tn++) {
            int c = colBase + wn * 32 + tn * 8 + 2 * tg;
            float bq0 = bq[c], bq1 = bq[c+1];
            float bk0 = bk[c], bk1 = bk[c+1];
            float bv0 = bv[c], bv1 = bv[c+1];
            float* A = aq[tm][tn];
            *(uint32_t*)(g_Qh + (size_t)r0 * DDIM + c) = f2h2(A[0] + bq0, A[1] + bq1);
            *(uint32_t*)(g_Qh + (size_t)r1 * DDIM + c) = f2h2(A[2] + bq0, A[3] + bq1);
            A = ak[tm][tn];
            *(uint32_t*)(g_Kh + (size_t)r0 * DDIM + c) = f2h2(A[0] + bk0, A[1] + bk1);
            *(uint32_t*)(g_Kh + (size_t)r1 * DDIM + c) = f2h2(A[2] + bk0, A[3] + bk1);
            A = avv[tm][tn];
            *(uint32_t*)(g_Vh + (size_t)r0 * DDIM + c) = f2h2(A[0] + bv0, A[1] + bv1);
            *(uint32_t*)(g_Vh + (size_t)r1 * DDIM + c) = f2h2(A[2] + bv0, A[3] + bv1);
        }
    }
}

// ============================================================
// Kernel 2b: transpose g_Vh [P][D] -> g_Vth [D][P], 128x128 tiles
// ============================================================
__global__ __launch_bounds__(256) void vt_kernel()
{
    __shared__ __half st[128][136];
    int px = blockIdx.x;   // feature tile 0..3
    int py = blockIdx.y;   // position tile 0..63
    int tid = threadIdx.x;
    int row = tid >> 1, h64 = (tid & 1) * 64;
    const __half* src = g_Vh + (size_t)(py * 128 + row) * DDIM + px * 128 + h64;
    #pragma unroll
    for (int i = 0; i < 8; i++)
        *(uint4*)&st[row][h64 + i * 8] = *(const uint4*)(src + i * 8);
    __syncthreads();
    int col = tid >> 1;
    __half tmp[64];
    #pragma unroll
    for (int j = 0; j < 64; j++) tmp[j] = st[h64 + j][col];
    __half* dst = g_Vth + (size_t)(px * 128 + col) * PP + py * 128 + h64;
    #pragma unroll
    for (int i = 0; i < 8; i++)
        *(uint4*)(dst + i * 8) = *(uint4*)&tmp[i * 8];
}

// ============================================================
// Kernel 3: tdiag[i] = (Q_i.K_i)/sqrt(d); also |Q_i|, |K_i| norms.
// ============================================================
__global__ void diag_kernel()
{
    int row = blockIdx.x, tid = threadIdx.x;   // 128 threads
    const __half* Q = g_Qh + (size_t)row * DDIM + tid * 4;
    const __half* K = g_Kh + (size_t)row * DDIM + tid * 4;
    uint2 qa = *(const uint2*)Q;
    uint2 ka = *(const uint2*)K;
    __half2 q0 = *(__half2*)&qa.x, q1 = *(__half2*)&qa.y;
    __half2 k0 = *(__half2*)&ka.x, k1 = *(__half2*)&ka.y;
    float2 qf0 = __half22float2(q0), qf1 = __half22float2(q1);
    float2 kf0 = __half22float2(k0), kf1 = __half22float2(k1);
    float s  = qf0.x*kf0.x + qf0.y*kf0.y + qf1.x*kf1.x + qf1.y*kf1.y;
    float qq = qf0.x*qf0.x + qf0.y*qf0.y + qf1.x*qf1.x + qf1.y*qf1.y;
    float kk = kf0.x*kf0.x + kf0.y*kf0.y + kf1.x*kf1.x + kf1.y*kf1.y;
    #pragma unroll
    for (int o = 16; o > 0; o >>= 1) {
        s  += __shfl_xor_sync(0xffffffffu, s, o);
        qq += __shfl_xor_sync(0xffffffffu, qq, o);
        kk += __shfl_xor_sync(0xffffffffu, kk, o);
    }
    __shared__ float rs[4], rq[4], rk[4];
    if ((tid & 31) == 0) { rs[tid >> 5] = s; rq[tid >> 5] = qq; rk[tid >> 5] = kk; }
    __syncthreads();
    if (tid == 0) {
        g_tdiag[row] = (rs[0] + rs[1] + rs[2] + rs[3]) * 0.044194173824159216f;
        g_qnorm[row] = sqrtf(rq[0] + rq[1] + rq[2] + rq[3]);
        g_knorm[row] = sqrtf(rk[0] + rk[1] + rk[2] + rk[3]);
    }
}

// ============================================================
// Kernel 3b: per-tile stats (max |Q|, max |K|, min tdiag)
// ============================================================
__global__ void tilestat_kernel()
{
    int b = blockIdx.x, tid = threadIdx.x;   // 128 threads
    int row = b * 128 + tid;
    float q = g_qnorm[row], k = g_knorm[row], t = g_tdiag[row];
    #pragma unroll
    for (int o = 16; o > 0; o >>= 1) {
        q = fmaxf(q, __shfl_xor_sync(0xffffffffu, q, o));
        k = fmaxf(k, __shfl_xor_sync(0xffffffffu, k, o));
        t = fminf(t, __shfl_xor_sync(0xffffffffu, t, o));
    }
    __shared__ float rq[4], rk[4], rt[4];
    if ((tid & 31) == 0) { rq[tid >> 5] = q; rk[tid >> 5] = k; rt[tid >> 5] = t; }
    __syncthreads();
    if (tid == 0) {
        g_Qmax[b]  = fmaxf(fmaxf(rq[0], rq[1]), fmaxf(rq[2], rq[3]));
        g_Kmax[b]  = fmaxf(fmaxf(rk[0], rk[1]), fmaxf(rk[2], rk[3]));
        g_tdmin[b] = fminf(fminf(rt[0], rt[1]), fminf(rt[2], rt[3]));
    }
}

// ============================================================
// Kernel 4: dist via G=FF^T, triangular-packed grid (2080 CTAs).
// Writes dist direct + mirrored; per-tile min dist -> g_dmin (both).
// ============================================================
__device__ __forceinline__ void ds_issue(uint32_t sbase, int stg, int kb, int tid,
    const __half* Fr, const __half* Fc)
{
    int row = tid >> 1;
    int ch0 = (tid & 1) * 2;
    uint32_t so = sbase + stg * 16384;
    size_t off = (size_t)row * DDIM + kb + ch0 * 8;
    cpa16(so +        swz64(row, ch0),     Fr + off);
    cpa16(so +        swz64(row, ch0 + 1), Fr + off + 8);
    cpa16(so + 8192 + swz64(row, ch0),     Fc + off);
    cpa16(so + 8192 + swz64(row, ch0 + 1), Fc + off + 8);
}

__global__ __launch_bounds__(256, 2) void dist_sym(float* __restrict__ dist_out)
{
    // triangular decode: t -> (bx <= by)
    int t = blockIdx.x;
    int by = (int)((sqrtf(8.f * t + 1.f) - 1.f) * 0.5f);
    while ((by + 1) * (by + 2) / 2 <= t) by++;
    while (by * (by + 1) / 2 > t) by--;
    int bx = t - by * (by + 1) / 2;

    extern __shared__ char dsm[];
    __shared__ float dmn[8];
    const uint32_t sbase = s2u(dsm);
    const int tid = threadIdx.x, lane = tid & 31, wid = tid >> 5;
    const int wm = wid & 3, wn = wid >> 2;
    const int rowBase = by * 128, colBase = bx * 128;

    float acc[2][8][4] = {};

    const __half* Fr = g_Fh + (size_t)rowBase * DDIM;
    const __half* Fc = g_Fh + (size_t)colBase * DDIM;

    const int NKB = DDIM / 32;   // 16
    #pragma unroll
    for (int s = 0; s < 3; s++) {
        ds_issue(sbase, s, s * 32, tid, Fr, Fc);
        cp_commit();
    }

    for (int kb = 0; kb < NKB; kb++) {
        cp_wait<2>();
        __syncthreads();
        if (kb + 3 < NKB)
            ds_issue(sbase, (kb + 3) & 3, (kb + 3) * 32, tid, Fr, Fc);
        cp_commit();

        uint32_t su = sbase + (kb & 3) * 16384;
        #pragma unroll
        for (int ks = 0; ks < 2; ks++) {
            uint32_t a[2][4];
            fragA(su, wm * 32,      ks, lane, a[0]);
            fragA(su, wm * 32 + 16, ks, lane, a[1]);
            #pragma unroll
            for (int p = 0; p < 4; p++) {
                uint32_t b[4];
                fragB(su + 8192, wn * 64 + p * 16, ks, lane, b);
                #pragma unroll
                for (int tm = 0; tm < 2; tm++) {
                    mma16(acc[tm][2*p],   a[tm], b);
                    mma16(acc[tm][2*p+1], a[tm], b + 2);
                }
            }
        }
    }
    cp_wait<0>();
    __syncthreads();

    // epilogue: dist = sqrt(max(nr + nc - 2G, 0)); direct + transpose; track min
    float* st = (float*)dsm;   // [128][132] floats
    const int gr = lane >> 2, tg = lane & 3;
    float locmin = 3.4e38f;
    #pragma unroll
    for (int tm = 0; tm < 2; tm++) {
        int rl0 = wm * 32 + tm * 16 + gr, rl1 = rl0 + 8;
        int r0 = rowBase + rl0, r1 = rowBase + rl1;
        float n0 = g_norm[r0], n1 = g_norm[r1];
        #pragma unroll
        for (int tn = 0; tn < 8; tn++) {
            int cl = wn * 64 + tn * 8 + 2 * tg;
            int c = colBase + cl;
            float nc0 = g_norm[c], nc1 = g_norm[c+1];
            float* A = acc[tm][tn];
            float d00 = sqrtf(fmaxf(n0 + nc0 - 2.f * A[0], 0.f));
            float d01 = sqrtf(fmaxf(n0 + nc1 - 2.f * A[1], 0.f));
            float d10 = sqrtf(fmaxf(n1 + nc0 - 2.f * A[2], 0.f));
            float d11 = sqrtf(fmaxf(n1 + nc1 - 2.f * A[3], 0.f));
            locmin = fminf(locmin, fminf(fminf(d00, d01), fminf(d10, d11)));
            *(float2*)(dist_out + (size_t)r0 * PP + c) = make_float2(d00, d01);
            *(float2*)(dist_out + (size_t)r1 * PP + c) = make_float2(d10, d11);
            st[(cl    ) * 132 + rl0] = d00;
            st[(cl + 1) * 132 + rl0] = d01;
            st[(cl    ) * 132 + rl1] = d10;
            st[(cl + 1) * 132 + rl1] = d11;
        }
    }
    #pragma unroll
    for (int o = 16; o > 0; o >>= 1) locmin = fminf(locmin, __shfl_xor_sync(0xffffffffu, locmin, o));
    if (lane == 0) dmn[wid] = locmin;
    __syncthreads();
    if (tid == 0) {
        float m = dmn[0];
        #pragma unroll
        for (int w = 1; w < 8; w++) m = fminf(m, dmn[w]);
        g_dmin[by * NT + bx] = m;
        g_dmin[bx * NT + by] = m;
    }
    if (bx != by) {
        int i = tid >> 1;
        int j0 = (tid & 1) * 64;
        const float* srow = st + i * 132 + j0;
        float* orow = dist_out + (size_t)(colBase + i) * PP + rowBase + j0;
        #pragma unroll
        for (int j = 0; j < 64; j += 4)
            *(float4*)(orow + j) = *(const float4*)(srow + j);
    }
}

// ============================================================
// Kernel 5: S=QK^T with provable tile skipping.
// ============================================================
__device__ __forceinline__ void ls_issue(uint32_t sbase, int stg, int kb, int tid,
    const __half* Qb, const __half* Kb)
{
    int row = tid >> 1;
    int ch0 = (tid & 1) * 2;
    uint32_t so = sbase + stg * 16384;
    size_t off = (size_t)row * DDIM + kb + ch0 * 8;
    cpa16(so +        swz64(row, ch0),     Qb + off);
    cpa16(so +        swz64(row, ch0 + 1), Qb + off + 8);
    cpa16(so + 8192 + swz64(row, ch0),     Kb + off);
    cpa16(so + 8192 + swz64(row, ch0 + 1), Kb + off + 8);
}

__global__ __launch_bounds__(256, 2) void logits_s(
    const float* __restrict__ lamP, const float* __restrict__ dist_in)
{
    const int bx = blockIdx.x, by = blockIdx.y;
    const int tid = threadIdx.x;
    const float lam = *lamP;
    const float isd = 0.044194173824159216f;  // 1/sqrt(512)

    float bound = isd * g_Qmax[by] * g_Kmax[bx] - g_tdmin[by] - lam * g_dmin[by * NT + bx];
    if (bound < -20.f) {
        if (tid == 0) g_skip[by * NT + bx] = 1;
        if (tid < 128) g_psum[(size_t)(by * 128 + tid) * NT + bx] = 0.f;
        return;
    }
    if (tid == 0) g_skip[by * NT + bx] = 0;

    extern __shared__ char dsm[];
    __shared__ float ps[128][2];
    const uint32_t sbase = s2u(dsm);
    const int lane = tid & 31, wid = tid >> 5;
    const int wm = wid & 3, wn = wid >> 2;
    const int rowBase = by * 128, colBase = bx * 128;

    float acc[2][8][4] = {};

    const __half* Qb = g_Qh + (size_t)rowBase * DDIM;
    const __half* Kb = g_Kh + (size_t)colBase * DDIM;

    const int NKB = DDIM / 32;   // 16
    #pragma unroll
    for (int s = 0; s < 3; s++) {
        ls_issue(sbase, s, s * 32, tid, Qb, Kb);
        cp_commit();
    }

    for (int kb = 0; kb < NKB; kb++) {
        cp_wait<2>();
        __syncthreads();
        if (kb + 3 < NKB)
            ls_issue(sbase, (kb + 3) & 3, (kb + 3) * 32, tid, Qb, Kb);
        cp_commit();

        uint32_t su = sbase + (kb & 3) * 16384;
        #pragma unroll
        for (int ks = 0; ks < 2; ks++) {
            uint32_t a[2][4];
            fragA(su, wm * 32,      ks, lane, a[0]);
            fragA(su, wm * 32 + 16, ks, lane, a[1]);
            #pragma unroll
            for (int p = 0; p < 4; p++) {
                uint32_t b[4];
                fragB(su + 8192, wn * 64 + p * 16, ks, lane, b);
                #pragma unroll
                for (int tm = 0; tm < 2; tm++) {
                    mma16(acc[tm][2*p],   a[tm], b);
                    mma16(acc[tm][2*p+1], a[tm], b + 2);
                }
            }
        }
    }

    const int gr = lane >> 2, tg = lane & 3;
    float rs[2][2];
    #pragma unroll
    for (int tm = 0; tm < 2; tm++) {
        int r0 = rowBase + wm * 32 + tm * 16 + gr, r1 = r0 + 8;
        float td0 = g_tdiag[r0], td1 = g_tdiag[r1];
        float s0 = 0.f, s1 = 0.f;
        #pragma unroll
        for (int tn = 0; tn < 8; tn++) {
            int c = colBase + wn * 64 + tn * 8 + 2 * tg;
            size_t o0 = (size_t)r0 * PP + c, o1 = (size_t)r1 * PP + c;
            float2 dd0 = *(const float2*)(dist_in + o0);
            float2 dd1 = *(const float2*)(dist_in + o1);
            float* S = acc[tm][tn];
            float e00 = __expf(fminf(S[0]*isd - lam*dd0.x - td0, 11.f));
            float e01 = __expf(fminf(S[1]*isd - lam*dd0.y - td0, 11.f));
            float e10 = __expf(fminf(S[2]*isd - lam*dd1.x - td1, 11.f));
            float e11 = __expf(fminf(S[3]*isd - lam*dd1.y - td1, 11.f));
            s0 += e00 + e01;
            s1 += e10 + e11;
            *(uint32_t*)(g_Th + o0) = f2h2(e00, e01);
            *(uint32_t*)(g_Th + o1) = f2h2(e10, e11);
        }
        rs[tm][0] = s0; rs[tm][1] = s1;
    }
    #pragma unroll
    for (int tm = 0; tm < 2; tm++) {
        #pragma unroll
        for (int h = 0; h < 2; h++) {
            float s = rs[tm][h];
            s += __shfl_xor_sync(0xffffffffu, s, 1);
            s += __shfl_xor_sync(0xffffffffu, s, 2);
            if (tg == 0) ps[wm * 32 + tm * 16 + gr + h * 8][wn] = s;
        }
    }
    __syncthreads();
    if (tid < 128)
        g_psum[(size_t)(rowBase + tid) * NT + bx] = ps[tid][0] + ps[tid][1];
}

// ============================================================
// Kernel 6: g_inv[row] = 1 / sum over 64 col-tile partials
// ============================================================
__global__ void rowsum_kernel()
{
    int row = blockIdx.x, lane = threadIdx.x;  // 32 threads
    const float* p = g_psum + (size_t)row * NT;
    float s = p[lane] + p[lane + 32];
    #pragma unroll
    for (int o = 16; o > 0; o >>= 1) s += __shfl_xor_sync(0xffffffffu, s, o);
    if (lane == 0) g_inv[row] = 1.f / s;
}

// ============================================================
// Kernel 7: F_out = (E @ V) * (1/sum). Skips all-zero col-tiles.
// ============================================================
__device__ __forceinline__ void av_issue(uint32_t sbase, int stg, int kOff, int tid,
    const __half* Ab, const __half* Bb)
{
    int row = tid >> 1;
    int ch0 = (tid & 1) * 2;
    uint32_t so = sbase + stg * 16384;
    size_t off = (size_t)row * PP + kOff + ch0 * 8;
    cpa16(so +        swz64(row, ch0),     Ab + off);
    cpa16(so +        swz64(row, ch0 + 1), Ab + off + 8);
    cpa16(so + 8192 + swz64(row, ch0),     Bb + off);
    cpa16(so + 8192 + swz64(row, ch0 + 1), Bb + off + 8);
}

__global__ __launch_bounds__(256, 2) void av_e(float* __restrict__ out)
{
    extern __shared__ char dsm[];
    __shared__ int act[NT];
    __shared__ int nactS;
    const uint32_t sbase = s2u(dsm);
    const int tid = threadIdx.x, lane = tid & 31, wid = tid >> 5;
    const int wm = wid & 3, wn = wid >> 2;
    const int rowBase = blockIdx.y * 128, colBase = blockIdx.x * 128;
    const int ry = blockIdx.y;

    if (tid == 0) {
        int n = 0;
        for (int ct = 0; ct < NT; ct++)
            if (!g_skip[ry * NT + ct]) act[n++] = ct;
        nactS = n;
    }
    __syncthreads();
    const int nch = nactS * 4;   // 4 k-chunks of 32 per active col-tile

    float acc[2][8][4] = {};

    const __half* Ab = g_Th  + (size_t)rowBase * PP;
    const __half* Bb = g_Vth + (size_t)colBase * PP;

    #pragma unroll
    for (int s = 0; s < 3; s++) {
        if (s < nch) av_issue(sbase, s, act[s >> 2] * 128 + (s & 3) * 32, tid, Ab, Bb);
        cp_commit();
    }

    for (int i = 0; i < nch; i++) {
        cp_wait<2>();
        __syncthreads();
        if (i + 3 < nch) {
            int j = i + 3;
            av_issue(sbase, j & 3, act[j >> 2] * 128 + (j & 3) * 32, tid, Ab, Bb);
        }
        cp_commit();

        uint32_t su = sbase + (i & 3) * 16384;
        #pragma unroll
        for (int ks = 0; ks < 2; ks++) {
            uint32_t a[2][4];
            fragA(su, wm * 32,      ks, lane, a[0]);
            fragA(su, wm * 32 + 16, ks, lane, a[1]);
            #pragma unroll
            for (int p = 0; p < 4; p++) {
                uint32_t b[4];
                fragB(su + 8192, wn * 64 + p * 16, ks, lane, b);
                #pragma unroll
                for (int tm = 0; tm < 2; tm++) {
                    mma16(acc[tm][2*p],   a[tm], b);
                    mma16(acc[tm][2*p+1], a[tm], b + 2);
                }
            }
        }
    }

    const int gr = lane >> 2, tg = lane & 3;
    #pragma unroll
    for (int tm = 0; tm < 2; tm++) {
        int r0 = rowBase + wm * 32 + tm * 16 + gr, r1 = r0 + 8;
        float i0 = g_inv[r0], i1 = g_inv[r1];
        #pragma unroll
        for (int tn = 0; tn < 8; tn++) {
            int c = colBase + wn * 64 + tn * 8 + 2 * tg;
            float* A = acc[tm][tn];
            *(float2*)(out + (size_t)r0 * DDIM + c) = make_float2(A[0]*i0, A[1]*i0);
            *(float2*)(out + (size_t)r1 * DDIM + c) = make_float2(A[2]*i1, A[3]*i1);
        }
    }
}

// ============================================================
extern "C" void kernel_launch(void* const* d_in, const int* in_sizes, int n_in,
                              void* d_out, int out_size)
{
    const float* F   = (const float*)d_in[0];
    const float* Wq  = (const float*)d_in[1];
    const float* bq  = (const float*)d_in[2];
    const float* Wk  = (const float*)d_in[3];
    const float* bk  = (const float*)d_in[4];
    const float* Wv  = (const float*)d_in[5];
    const float* bv  = (const float*)d_in[6];
    const float* lam = (const float*)d_in[7];

    float* out  = (float*)d_out;
    float* Fout = out;                        // [P, D]
    float* dist = out + (size_t)PP * DDIM;    // [P, P]

    static bool attr_done = false;
    if (!attr_done) {
        cudaFuncSetAttribute(qkv_h,    cudaFuncAttributeMaxDynamicSharedMemorySize, 81920);
        cudaFuncSetAttribute(dist_sym, cudaFuncAttributeMaxDynamicSharedMemorySize, 69632);
        cudaFuncSetAttribute(logits_s, cudaFuncAttributeMaxDynamicSharedMemorySize, 65536);
        cudaFuncSetAttribute(av_e,     cudaFuncAttributeMaxDynamicSharedMemorySize, 65536);
        attr_done = true;
    }

    wcvt_kernel<<<dim3(256, 3), 256>>>(Wq, Wk, Wv);
    norm_cvt_kernel<<<PP/8, 256>>>(F);
    qkv_h<<<dim3(DDIM/64, PP/128), 256, 81920>>>(bq, bk, bv);
    vt_kernel<<<dim3(DDIM/128, PP/128), 256>>>();
    diag_kernel<<<PP, 128>>>();
    tilestat_kernel<<<NT, 128>>>();
    dist_sym<<<NT * (NT + 1) / 2, 256, 69632>>>(dist);
    logits_s<<<dim3(NT, NT), 256, 65536>>>(lam, dist);
    rowsum_kernel<<<PP, 32>>>();
    av_e<<<dim3(DDIM/128, PP/128), 256, 65536>>>(Fout);
}

// round 17
// speedup vs baseline: 2.3827x; 1.0302x over previous
#include <cuda_runtime.h>
#include <cuda_fp16.h>
#include <math.h>
#include <stdint.h>

#define PP 8192
#define DDIM 512
#define NT 64   // number of 128-wide tiles per dimension
#define NQKV 512            // qkv CTAs: (DDIM/64) * (PP/128) = 8*64
#define NDIST (NT*(NT+1)/2) // 2080 triangular dist CTAs

// ---- scratch (device globals) ----
__device__ __half g_Qh[PP * DDIM];
__device__ __half g_Kh[PP * DDIM];
__device__ __half g_Fh[PP * DDIM];
__device__ __half g_Vh[PP * DDIM];           // V row-major [position][feature]
__device__ __half g_Vth[DDIM * PP];          // V transposed: [feature][position]
__device__ __half g_Wh[3 * DDIM * DDIM];     // fp16 weights: Wq, Wk, Wv
__device__ __half g_Th[(size_t)PP * PP];     // unnormalized exp probs (fp16), 128 MB
__device__ float  g_psum[(size_t)PP * NT];   // per (row, colTile) partial sums
__device__ float  g_norm[PP];
__device__ float  g_tdiag[PP];
__device__ float  g_inv[PP];
__device__ float  g_qnorm[PP];
__device__ float  g_knorm[PP];
__device__ float  g_Qmax[NT];
__device__ float  g_Kmax[NT];
__device__ float  g_tdmin[NT];
__device__ float  g_dmin[NT * NT];
__device__ unsigned char g_skip[NT * NT];

// ---------------- helpers ----------------
__device__ __forceinline__ uint32_t s2u(const void* p) {
    return (uint32_t)__cvta_generic_to_shared(p);
}
__device__ __forceinline__ uint32_t f2h2(float a, float b) {
    __half2 h = __floats2half2_rn(a, b);
    return *reinterpret_cast<uint32_t*>(&h);
}
// tile rows of 32 halves (64B), 16B chunks XOR-swizzled
__device__ __forceinline__ int swz64(int r, int c) {
    return r * 64 + ((c ^ ((r >> 1) & 3)) << 4);
}
__device__ __forceinline__ void mma16(float* d, const uint32_t* a, const uint32_t* b) {
    asm volatile(
        "mma.sync.aligned.m16n8k16.row.col.f32.f16.f16.f32 "
        "{%0,%1,%2,%3},{%4,%5,%6,%7},{%8,%9},{%0,%1,%2,%3};"
        : "+f"(d[0]), "+f"(d[1]), "+f"(d[2]), "+f"(d[3])
        : "r"(a[0]), "r"(a[1]), "r"(a[2]), "r"(a[3]), "r"(b[0]), "r"(b[1]));
}
__device__ __forceinline__ void ldsm4(uint32_t addr, uint32_t* r) {
    asm volatile("ldmatrix.sync.aligned.m8n8.x4.shared.b16 {%0,%1,%2,%3}, [%4];"
        : "=r"(r[0]), "=r"(r[1]), "=r"(r[2]), "=r"(r[3]) : "r"(addr));
}
__device__ __forceinline__ void fragA(uint32_t tbase, int R, int ks, int lane, uint32_t* a) {
    int mi = lane >> 3, ri = lane & 7;
    int r = R + ri + (mi & 1) * 8;
    int c = ks * 2 + (mi >> 1);
    ldsm4(tbase + swz64(r, c), a);
}
__device__ __forceinline__ void fragB(uint32_t tbase, int N0, int ks, int lane, uint32_t* b) {
    int mi = lane >> 3, ri = lane & 7;
    int r = N0 + ri + (mi >> 1) * 8;
    int c = ks * 2 + (mi & 1);
    ldsm4(tbase + swz64(r, c), b);
}
// ---- cp.async ----
__device__ __forceinline__ void cpa16(uint32_t dst, const void* src) {
    asm volatile("cp.async.cg.shared.global [%0], [%1], 16;" :: "r"(dst), "l"(src));
}
__device__ __forceinline__ void cp_commit() {
    asm volatile("cp.async.commit_group;" ::: "memory");
}
template<int N>
__device__ __forceinline__ void cp_wait() {
    asm volatile("cp.async.wait_group %0;" :: "n"(N) : "memory");
}

// ============================================================
// Kernel 0: convert weights to fp16 (same rounding as before)
// ============================================================
__global__ void wcvt_kernel(const float* __restrict__ Wq,
                            const float* __restrict__ Wk,
                            const float* __restrict__ Wv)
{
    const float* src = (blockIdx.y == 0) ? Wq : (blockIdx.y == 1) ? Wk : Wv;
    __half* dst = g_Wh + (size_t)blockIdx.y * DDIM * DDIM;
    int i = (blockIdx.x * 256 + threadIdx.x) * 4;
    float4 v = *(const float4*)(src + i);
    uint2 h; h.x = f2h2(v.x, v.y); h.y = f2h2(v.z, v.w);
    *(uint2*)(dst + i) = h;
}

// ============================================================
// Kernel 1: row norms of F + convert F -> g_Fh. Warp per row.
// ============================================================
__global__ __launch_bounds__(256) void norm_cvt_kernel(const float* __restrict__ F)
{
    int warp = threadIdx.x >> 5, lane = threadIdx.x & 31;
    int row = blockIdx.x * 8 + warp;
    const float4* fr = (const float4*)(F + (size_t)row * DDIM);
    __half* fh = g_Fh + (size_t)row * DDIM;
    float s = 0.f;
    #pragma unroll
    for (int i = 0; i < 4; i++) {
        float4 v = fr[lane + i * 32];
        s += v.x*v.x + v.y*v.y + v.z*v.z + v.w*v.w;
        uint2 h; h.x = f2h2(v.x, v.y); h.y = f2h2(v.z, v.w);
        *(uint2*)(fh + (lane + i * 32) * 4) = h;
    }
    #pragma unroll
    for (int o = 16; o > 0; o >>= 1) s += __shfl_xor_sync(0xffffffffu, s, o);
    if (lane == 0) g_norm[row] = s;
}

// ============================================================
// Merged kernel: qkv CTAs (blockIdx.x < NQKV) + dist CTAs (rest).
// Both paths independent; interleaving fills tensor-idle slots.
// ============================================================
__device__ __forceinline__ void qk_issue(uint32_t sbase, int stg, int kb, int tid,
    const __half* Fb, const __half* W0, const __half* W1, const __half* W2)
{
    uint32_t so = sbase + stg * 20480;
    int row = tid >> 1, ch0 = (tid & 1) * 2;
    size_t offA = (size_t)row * DDIM + kb + ch0 * 8;
    cpa16(so + swz64(row, ch0),     Fb + offA);
    cpa16(so + swz64(row, ch0 + 1), Fb + offA + 8);
    int brow = tid >> 2, bch = tid & 3;
    size_t offB = (size_t)brow * DDIM + kb + bch * 8;
    cpa16(so +  8192 + swz64(brow, bch), W0 + offB);
    cpa16(so + 12288 + swz64(brow, bch), W1 + offB);
    cpa16(so + 16384 + swz64(brow, bch), W2 + offB);
}
__device__ __forceinline__ void ds_issue(uint32_t sbase, int stg, int kb, int tid,
    const __half* Fr, const __half* Fc)
{
    int row = tid >> 1;
    int ch0 = (tid & 1) * 2;
    uint32_t so = sbase + stg * 16384;
    size_t off = (size_t)row * DDIM + kb + ch0 * 8;
    cpa16(so +        swz64(row, ch0),     Fr + off);
    cpa16(so +        swz64(row, ch0 + 1), Fr + off + 8);
    cpa16(so + 8192 + swz64(row, ch0),     Fc + off);
    cpa16(so + 8192 + swz64(row, ch0 + 1), Fc + off + 8);
}

__global__ __launch_bounds__(256, 2) void qkv_dist(
    const float* __restrict__ bq, const float* __restrict__ bk,
    const float* __restrict__ bv, float* __restrict__ dist_out)
{
    extern __shared__ char dsm[];
    const uint32_t sbase = s2u(dsm);
    const int tid = threadIdx.x, lane = tid & 31, wid = tid >> 5;
    const int wm = wid & 3, wn = wid >> 2;
    const int NKB = DDIM / 32;   // 16

    if (blockIdx.x < NQKV) {
        // ---------------- qkv path ----------------
        const int bxq = blockIdx.x & 7;        // 8 col tiles of 64
        const int byq = blockIdx.x >> 3;       // 64 row tiles of 128
        const int rowBase = byq * 128, colBase = bxq * 64;

        float aq[2][4][4] = {}, ak[2][4][4] = {}, avv[2][4][4] = {};

        const __half* Fb = g_Fh + (size_t)rowBase * DDIM;
        const __half* W0 = g_Wh + (size_t)colBase * DDIM;
        const __half* W1 = g_Wh + (size_t)DDIM * DDIM     + (size_t)colBase * DDIM;
        const __half* W2 = g_Wh + (size_t)DDIM * DDIM * 2 + (size_t)colBase * DDIM;

        #pragma unroll
        for (int s = 0; s < 3; s++) {
            qk_issue(sbase, s, s * 32, tid, Fb, W0, W1, W2);
            cp_commit();
        }
        for (int kb = 0; kb < NKB; kb++) {
            cp_wait<2>();
            __syncthreads();
            if (kb + 3 < NKB)
                qk_issue(sbase, (kb + 3) & 3, (kb + 3) * 32, tid, Fb, W0, W1, W2);
            cp_commit();

            uint32_t su = sbase + (kb & 3) * 20480;
            #pragma unroll
            for (int ks = 0; ks < 2; ks++) {
                uint32_t a[2][4];
                fragA(su, wm * 32,      ks, lane, a[0]);
                fragA(su, wm * 32 + 16, ks, lane, a[1]);
                #pragma unroll
                for (int p = 0; p < 2; p++) {
                    uint32_t b[4];
                    fragB(su + 8192, wn * 32 + p * 16, ks, lane, b);
                    #pragma unroll
                    for (int tm = 0; tm < 2; tm++) {
                        mma16(aq[tm][2*p],   a[tm], b);
                        mma16(aq[tm][2*p+1], a[tm], b + 2);
                    }
                    fragB(su + 12288, wn * 32 + p * 16, ks, lane, b);
                    #pragma unroll
                    for (int tm = 0; tm < 2; tm++) {
                        mma16(ak[tm][2*p],   a[tm], b);
                        mma16(ak[tm][2*p+1], a[tm], b + 2);
                    }
                    fragB(su + 16384, wn * 32 + p * 16, ks, lane, b);
                    #pragma unroll
                    for (int tm = 0; tm < 2; tm++) {
                        mma16(avv[tm][2*p],   a[tm], b);
                        mma16(avv[tm][2*p+1], a[tm], b + 2);
                    }
                }
            }
        }

        const int gr = lane >> 2, tg = lane & 3;
        #pragma unroll
        for (int tm = 0; tm < 2; tm++) {
            int r0 = rowBase + wm * 32 + tm * 16 + gr, r1 = r0 + 8;
            #pragma unroll
            for (int tn = 0; tn < 4; tn++) {
                int c = colBase + wn * 32 + tn * 8 + 2 * tg;
                float bq0 = bq[c], bq1 = bq[c+1];
                float bk0 = bk[c], bk1 = bk[c+1];
                float bv0 = bv[c], bv1 = bv[c+1];
                float* A = aq[tm][tn];
                *(uint32_t*)(g_Qh + (size_t)r0 * DDIM + c) = f2h2(A[0] + bq0, A[1] + bq1);
                *(uint32_t*)(g_Qh + (size_t)r1 * DDIM + c) = f2h2(A[2] + bq0, A[3] + bq1);
                A = ak[tm][tn];
                *(uint32_t*)(g_Kh + (size_t)r0 * DDIM + c) = f2h2(A[0] + bk0, A[1] + bk1);
                *(uint32_t*)(g_Kh + (size_t)r1 * DDIM + c) = f2h2(A[2] + bk0, A[3] + bk1);
                A = avv[tm][tn];
                *(uint32_t*)(g_Vh + (size_t)r0 * DDIM + c) = f2h2(A[0] + bv0, A[1] + bv1);
                *(uint32_t*)(g_Vh + (size_t)r1 * DDIM + c) = f2h2(A[2] + bv0, A[3] + bv1);
            }
        }
        return;
    }

    // ---------------- dist path (triangular) ----------------
    int t = blockIdx.x - NQKV;
    int by = (int)((sqrtf(8.f * t + 1.f) - 1.f) * 0.5f);
    while ((by + 1) * (by + 2) / 2 <= t) by++;
    while (by * (by + 1) / 2 > t) by--;
    int bx = t - by * (by + 1) / 2;

    __shared__ float dmn[8];
    const int rowBase = by * 128, colBase = bx * 128;

    float acc[2][8][4] = {};

    const __half* Fr = g_Fh + (size_t)rowBase * DDIM;
    const __half* Fc = g_Fh + (size_t)colBase * DDIM;

    #pragma unroll
    for (int s = 0; s < 3; s++) {
        ds_issue(sbase, s, s * 32, tid, Fr, Fc);
        cp_commit();
    }
    for (int kb = 0; kb < NKB; kb++) {
        cp_wait<2>();
        __syncthreads();
        if (kb + 3 < NKB)
            ds_issue(sbase, (kb + 3) & 3, (kb + 3) * 32, tid, Fr, Fc);
        cp_commit();

        uint32_t su = sbase + (kb & 3) * 16384;
        #pragma unroll
        for (int ks = 0; ks < 2; ks++) {
            uint32_t a[2][4];
            fragA(su, wm * 32,      ks, lane, a[0]);
            fragA(su, wm * 32 + 16, ks, lane, a[1]);
            #pragma unroll
            for (int p = 0; p < 4; p++) {
                uint32_t b[4];
                fragB(su + 8192, wn * 64 + p * 16, ks, lane, b);
                #pragma unroll
                for (int tm = 0; tm < 2; tm++) {
                    mma16(acc[tm][2*p],   a[tm], b);
                    mma16(acc[tm][2*p+1], a[tm], b + 2);
                }
            }
        }
    }
    cp_wait<0>();
    __syncthreads();

    // epilogue: dist = sqrt(max(nr + nc - 2G, 0)); direct + transpose; track min
    float* st = (float*)dsm;   // [128][132] floats
    const int gr = lane >> 2, tg = lane & 3;
    float locmin = 3.4e38f;
    #pragma unroll
    for (int tm = 0; tm < 2; tm++) {
        int rl0 = wm * 32 + tm * 16 + gr, rl1 = rl0 + 8;
        int r0 = rowBase + rl0, r1 = rowBase + rl1;
        float n0 = g_norm[r0], n1 = g_norm[r1];
        #pragma unroll
        for (int tn = 0; tn < 8; tn++) {
            int cl = wn * 64 + tn * 8 + 2 * tg;
            int c = colBase + cl;
            float nc0 = g_norm[c], nc1 = g_norm[c+1];
            float* A = acc[tm][tn];
            float d00 = sqrtf(fmaxf(n0 + nc0 - 2.f * A[0], 0.f));
            float d01 = sqrtf(fmaxf(n0 + nc1 - 2.f * A[1], 0.f));
            float d10 = sqrtf(fmaxf(n1 + nc0 - 2.f * A[2], 0.f));
            float d11 = sqrtf(fmaxf(n1 + nc1 - 2.f * A[3], 0.f));
            locmin = fminf(locmin, fminf(fminf(d00, d01), fminf(d10, d11)));
            *(float2*)(dist_out + (size_t)r0 * PP + c) = make_float2(d00, d01);
            *(float2*)(dist_out + (size_t)r1 * PP + c) = make_float2(d10, d11);
            st[(cl    ) * 132 + rl0] = d00;
            st[(cl + 1) * 132 + rl0] = d01;
            st[(cl    ) * 132 + rl1] = d10;
            st[(cl + 1) * 132 + rl1] = d11;
        }
    }
    #pragma unroll
    for (int o = 16; o > 0; o >>= 1) locmin = fminf(locmin, __shfl_xor_sync(0xffffffffu, locmin, o));
    if (lane == 0) dmn[wid] = locmin;
    __syncthreads();
    if (tid == 0) {
        float m = dmn[0];
        #pragma unroll
        for (int w = 1; w < 8; w++) m = fminf(m, dmn[w]);
        g_dmin[by * NT + bx] = m;
        g_dmin[bx * NT + by] = m;
    }
    if (bx != by) {
        int i = tid >> 1;
        int j0 = (tid & 1) * 64;
        const float* srow = st + i * 132 + j0;
        float* orow = dist_out + (size_t)(colBase + i) * PP + rowBase + j0;
        #pragma unroll
        for (int j = 0; j < 64; j += 4)
            *(float4*)(orow + j) = *(const float4*)(srow + j);
    }
}

// ============================================================
// Kernel 2b: transpose g_Vh [P][D] -> g_Vth [D][P], 128x128 tiles
// ============================================================
__global__ __launch_bounds__(256) void vt_kernel()
{
    __shared__ __half st[128][136];
    int px = blockIdx.x;   // feature tile 0..3
    int py = blockIdx.y;   // position tile 0..63
    int tid = threadIdx.x;
    int row = tid >> 1, h64 = (tid & 1) * 64;
    const __half* src = g_Vh + (size_t)(py * 128 + row) * DDIM + px * 128 + h64;
    #pragma unroll
    for (int i = 0; i < 8; i++)
        *(uint4*)&st[row][h64 + i * 8] = *(const uint4*)(src + i * 8);
    __syncthreads();
    int col = tid >> 1;
    __half tmp[64];
    #pragma unroll
    for (int j = 0; j < 64; j++) tmp[j] = st[h64 + j][col];
    __half* dst = g_Vth + (size_t)(px * 128 + col) * PP + py * 128 + h64;
    #pragma unroll
    for (int i = 0; i < 8; i++)
        *(uint4*)(dst + i * 8) = *(uint4*)&tmp[i * 8];
}

// ============================================================
// Kernel 3: tdiag/qnorm/knorm. Warp per row, 8 rows/block.
// ============================================================
__global__ __launch_bounds__(256) void diag_kernel()
{
    int warp = threadIdx.x >> 5, lane = threadIdx.x & 31;
    int row = blockIdx.x * 8 + warp;
    const __half* Q = g_Qh + (size_t)row * DDIM;
    const __half* K = g_Kh + (size_t)row * DDIM;
    float s = 0.f, qq = 0.f, kk = 0.f;
    #pragma unroll
    for (int i = 0; i < 4; i++) {
        int o4 = (lane + i * 32) * 4;
        uint2 qa = *(const uint2*)(Q + o4);
        uint2 ka = *(const uint2*)(K + o4);
        __half2 q0 = *(__half2*)&qa.x, q1 = *(__half2*)&qa.y;
        __half2 k0 = *(__half2*)&ka.x, k1 = *(__half2*)&ka.y;
        float2 qf0 = __half22float2(q0), qf1 = __half22float2(q1);
        float2 kf0 = __half22float2(k0), kf1 = __half22float2(k1);
        s  += qf0.x*kf0.x + qf0.y*kf0.y + qf1.x*kf1.x + qf1.y*kf1.y;
        qq += qf0.x*qf0.x + qf0.y*qf0.y + qf1.x*qf1.x + qf1.y*qf1.y;
        kk += kf0.x*kf0.x + kf0.y*kf0.y + kf1.x*kf1.x + kf1.y*kf1.y;
    }
    #pragma unroll
    for (int o = 16; o > 0; o >>= 1) {
        s  += __shfl_xor_sync(0xffffffffu, s, o);
        qq += __shfl_xor_sync(0xffffffffu, qq, o);
        kk += __shfl_xor_sync(0xffffffffu, kk, o);
    }
    if (lane == 0) {
        g_tdiag[row] = s * 0.044194173824159216f;
        g_qnorm[row] = sqrtf(qq);
        g_knorm[row] = sqrtf(kk);
    }
}

// ============================================================
// Kernel 3b: per-tile stats (max |Q|, max |K|, min tdiag)
// ============================================================
__global__ void tilestat_kernel()
{
    int b = blockIdx.x, tid = threadIdx.x;   // 128 threads
    int row = b * 128 + tid;
    float q = g_qnorm[row], k = g_knorm[row], t = g_tdiag[row];
    #pragma unroll
    for (int o = 16; o > 0; o >>= 1) {
        q = fmaxf(q, __shfl_xor_sync(0xffffffffu, q, o));
        k = fmaxf(k, __shfl_xor_sync(0xffffffffu, k, o));
        t = fminf(t, __shfl_xor_sync(0xffffffffu, t, o));
    }
    __shared__ float rq[4], rk[4], rt[4];
    if ((tid & 31) == 0) { rq[tid >> 5] = q; rk[tid >> 5] = k; rt[tid >> 5] = t; }
    __syncthreads();
    if (tid == 0) {
        g_Qmax[b]  = fmaxf(fmaxf(rq[0], rq[1]), fmaxf(rq[2], rq[3]));
        g_Kmax[b]  = fmaxf(fmaxf(rk[0], rk[1]), fmaxf(rk[2], rk[3]));
        g_tdmin[b] = fminf(fminf(rt[0], rt[1]), fminf(rt[2], rt[3]));
    }
}

// ============================================================
// Kernel 5: S=QK^T with provable tile skipping.
// ============================================================
__device__ __forceinline__ void ls_issue(uint32_t sbase, int stg, int kb, int tid,
    const __half* Qb, const __half* Kb)
{
    int row = tid >> 1;
    int ch0 = (tid & 1) * 2;
    uint32_t so = sbase + stg * 16384;
    size_t off = (size_t)row * DDIM + kb + ch0 * 8;
    cpa16(so +        swz64(row, ch0),     Qb + off);
    cpa16(so +        swz64(row, ch0 + 1), Qb + off + 8);
    cpa16(so + 8192 + swz64(row, ch0),     Kb + off);
    cpa16(so + 8192 + swz64(row, ch0 + 1), Kb + off + 8);
}

__global__ __launch_bounds__(256, 2) void logits_s(
    const float* __restrict__ lamP, const float* __restrict__ dist_in)
{
    const int bx = blockIdx.x, by = blockIdx.y;
    const int tid = threadIdx.x;
    const float lam = *lamP;
    const float isd = 0.044194173824159216f;  // 1/sqrt(512)

    float bound = isd * g_Qmax[by] * g_Kmax[bx] - g_tdmin[by] - lam * g_dmin[by * NT + bx];
    if (bound < -20.f) {
        if (tid == 0) g_skip[by * NT + bx] = 1;
        if (tid < 128) g_psum[(size_t)(by * 128 + tid) * NT + bx] = 0.f;
        return;
    }
    if (tid == 0) g_skip[by * NT + bx] = 0;

    extern __shared__ char dsm[];
    __shared__ float ps[128][2];
    const uint32_t sbase = s2u(dsm);
    const int lane = tid & 31, wid = tid >> 5;
    const int wm = wid & 3, wn = wid >> 2;
    const int rowBase = by * 128, colBase = bx * 128;

    float acc[2][8][4] = {};

    const __half* Qb = g_Qh + (size_t)rowBase * DDIM;
    const __half* Kb = g_Kh + (size_t)colBase * DDIM;

    const int NKB = DDIM / 32;   // 16
    #pragma unroll
    for (int s = 0; s < 3; s++) {
        ls_issue(sbase, s, s * 32, tid, Qb, Kb);
        cp_commit();
    }

    for (int kb = 0; kb < NKB; kb++) {
        cp_wait<2>();
        __syncthreads();
        if (kb + 3 < NKB)
            ls_issue(sbase, (kb + 3) & 3, (kb + 3) * 32, tid, Qb, Kb);
        cp_commit();

        uint32_t su = sbase + (kb & 3) * 16384;
        #pragma unroll
        for (int ks = 0; ks < 2; ks++) {
            uint32_t a[2][4];
            fragA(su, wm * 32,      ks, lane, a[0]);
            fragA(su, wm * 32 + 16, ks, lane, a[1]);
            #pragma unroll
            for (int p = 0; p < 4; p++) {
                uint32_t b[4];
                fragB(su + 8192, wn * 64 + p * 16, ks, lane, b);
                #pragma unroll
                for (int tm = 0; tm < 2; tm++) {
                    mma16(acc[tm][2*p],   a[tm], b);
                    mma16(acc[tm][2*p+1], a[tm], b + 2);
                }
            }
        }
    }

    const int gr = lane >> 2, tg = lane & 3;
    float rs[2][2];
    #pragma unroll
    for (int tm = 0; tm < 2; tm++) {
        int r0 = rowBase + wm * 32 + tm * 16 + gr, r1 = r0 + 8;
        float td0 = g_tdiag[r0], td1 = g_tdiag[r1];
        float s0 = 0.f, s1 = 0.f;
        #pragma unroll
        for (int tn = 0; tn < 8; tn++) {
            int c = colBase + wn * 64 + tn * 8 + 2 * tg;
            size_t o0 = (size_t)r0 * PP + c, o1 = (size_t)r1 * PP + c;
            float2 dd0 = *(const float2*)(dist_in + o0);
            float2 dd1 = *(const float2*)(dist_in + o1);
            float* S = acc[tm][tn];
            float e00 = __expf(fminf(S[0]*isd - lam*dd0.x - td0, 11.f));
            float e01 = __expf(fminf(S[1]*isd - lam*dd0.y - td0, 11.f));
            float e10 = __expf(fminf(S[2]*isd - lam*dd1.x - td1, 11.f));
            float e11 = __expf(fminf(S[3]*isd - lam*dd1.y - td1, 11.f));
            s0 += e00 + e01;
            s1 += e10 + e11;
            *(uint32_t*)(g_Th + o0) = f2h2(e00, e01);
            *(uint32_t*)(g_Th + o1) = f2h2(e10, e11);
        }
        rs[tm][0] = s0; rs[tm][1] = s1;
    }
    #pragma unroll
    for (int tm = 0; tm < 2; tm++) {
        #pragma unroll
        for (int h = 0; h < 2; h++) {
            float s = rs[tm][h];
            s += __shfl_xor_sync(0xffffffffu, s, 1);
            s += __shfl_xor_sync(0xffffffffu, s, 2);
            if (tg == 0) ps[wm * 32 + tm * 16 + gr + h * 8][wn] = s;
        }
    }
    __syncthreads();
    if (tid < 128)
        g_psum[(size_t)(rowBase + tid) * NT + bx] = ps[tid][0] + ps[tid][1];
}

// ============================================================
// Kernel 6: g_inv[row] = 1 / sum over 64 col-tile partials
// ============================================================
__global__ void rowsum_kernel()
{
    int row = blockIdx.x, lane = threadIdx.x;  // 32 threads
    const float* p = g_psum + (size_t)row * NT;
    float s = p[lane] + p[lane + 32];
    #pragma unroll
    for (int o = 16; o > 0; o >>= 1) s += __shfl_xor_sync(0xffffffffu, s, o);
    if (lane == 0) g_inv[row] = 1.f / s;
}

// ============================================================
// Kernel 7: F_out = (E @ V) * (1/sum). Skips all-zero col-tiles.
// ============================================================
__device__ __forceinline__ void av_issue(uint32_t sbase, int stg, int kOff, int tid,
    const __half* Ab, const __half* Bb)
{
    int row = tid >> 1;
    int ch0 = (tid & 1) * 2;
    uint32_t so = sbase + stg * 16384;
    size_t off = (size_t)row * PP + kOff + ch0 * 8;
    cpa16(so +        swz64(row, ch0),     Ab + off);
    cpa16(so +        swz64(row, ch0 + 1), Ab + off + 8);
    cpa16(so + 8192 + swz64(row, ch0),     Bb + off);
    cpa16(so + 8192 + swz64(row, ch0 + 1), Bb + off + 8);
}

__global__ __launch_bounds__(256, 2) void av_e(float* __restrict__ out)
{
    extern __shared__ char dsm[];
    __shared__ int act[NT];
    __shared__ int nactS;
    const uint32_t sbase = s2u(dsm);
    const int tid = threadIdx.x, lane = tid & 31, wid = tid >> 5;
    const int wm = wid & 3, wn = wid >> 2;
    const int rowBase = blockIdx.y * 128, colBase = blockIdx.x * 128;
    const int ry = blockIdx.y;

    if (tid == 0) {
        int n = 0;
        for (int ct = 0; ct < NT; ct++)
            if (!g_skip[ry * NT + ct]) act[n++] = ct;
        nactS = n;
    }
    __syncthreads();
    const int nch = nactS * 4;   // 4 k-chunks of 32 per active col-tile

    float acc[2][8][4] = {};

    const __half* Ab = g_Th  + (size_t)rowBase * PP;
    const __half* Bb = g_Vth + (size_t)colBase * PP;

    #pragma unroll
    for (int s = 0; s < 3; s++) {
        if (s < nch) av_issue(sbase, s, act[s >> 2] * 128 + (s & 3) * 32, tid, Ab, Bb);
        cp_commit();
    }

    for (int i = 0; i < nch; i++) {
        cp_wait<2>();
        __syncthreads();
        if (i + 3 < nch) {
            int j = i + 3;
            av_issue(sbase, j & 3, act[j >> 2] * 128 + (j & 3) * 32, tid, Ab, Bb);
        }
        cp_commit();

        uint32_t su = sbase + (i & 3) * 16384;
        #pragma unroll
        for (int ks = 0; ks < 2; ks++) {
            uint32_t a[2][4];
            fragA(su, wm * 32,      ks, lane, a[0]);
            fragA(su, wm * 32 + 16, ks, lane, a[1]);
            #pragma unroll
            for (int p = 0; p < 4; p++) {
                uint32_t b[4];
                fragB(su + 8192, wn * 64 + p * 16, ks, lane, b);
                #pragma unroll
                for (int tm = 0; tm < 2; tm++) {
                    mma16(acc[tm][2*p],   a[tm], b);
                    mma16(acc[tm][2*p+1], a[tm], b + 2);
                }
            }
        }
    }

    const int gr = lane >> 2, tg = lane & 3;
    #pragma unroll
    for (int tm = 0; tm < 2; tm++) {
        int r0 = rowBase + wm * 32 + tm * 16 + gr, r1 = r0 + 8;
        float i0 = g_inv[r0], i1 = g_inv[r1];
        #pragma unroll
        for (int tn = 0; tn < 8; tn++) {
            int c = colBase + wn * 64 + tn * 8 + 2 * tg;
            float* A = acc[tm][tn];
            *(float2*)(out + (size_t)r0 * DDIM + c) = make_float2(A[0]*i0, A[1]*i0);
            *(float2*)(out + (size_t)r1 * DDIM + c) = make_float2(A[2]*i1, A[3]*i1);
        }
    }
}

// ============================================================
extern "C" void kernel_launch(void* const* d_in, const int* in_sizes, int n_in,
                              void* d_out, int out_size)
{
    const float* F   = (const float*)d_in[0];
    const float* Wq  = (const float*)d_in[1];
    const float* bq  = (const float*)d_in[2];
    const float* Wk  = (const float*)d_in[3];
    const float* bk  = (const float*)d_in[4];
    const float* Wv  = (const float*)d_in[5];
    const float* bv  = (const float*)d_in[6];
    const float* lam = (const float*)d_in[7];

    float* out  = (float*)d_out;
    float* Fout = out;                        // [P, D]
    float* dist = out + (size_t)PP * DDIM;    // [P, P]

    static bool attr_done = false;
    if (!attr_done) {
        cudaFuncSetAttribute(qkv_dist, cudaFuncAttributeMaxDynamicSharedMemorySize, 81920);
        cudaFuncSetAttribute(logits_s, cudaFuncAttributeMaxDynamicSharedMemorySize, 65536);
        cudaFuncSetAttribute(av_e,     cudaFuncAttributeMaxDynamicSharedMemorySize, 65536);
        attr_done = true;
    }

    wcvt_kernel<<<dim3(256, 3), 256>>>(Wq, Wk, Wv);
    norm_cvt_kernel<<<PP/8, 256>>>(F);
    qkv_dist<<<NQKV + NDIST, 256, 81920>>>(bq, bk, bv, dist);
    vt_kernel<<<dim3(DDIM/128, PP/128), 256>>>();
    diag_kernel<<<PP/8, 256>>>();
    tilestat_kernel<<<NT, 128>>>();
    logits_s<<<dim3(NT, NT), 256, 65536>>>(lam, dist);
    rowsum_kernel<<<PP, 32>>>();
    av_e<<<dim3(DDIM/128, PP/128), 256, 65536>>>(Fout);
}